// round 1
// baseline (speedup 1.0000x reference)
#include <cuda_runtime.h>
#include <math.h>
#include <stdint.h>

#define NTOK   8192     // B*S
#define DMODEL 512
#define HEADS  8
#define HD     64
#define SEQ    1024
#define BATCH  8
#define FFDIM  2048
#define NSLOTS 512
#define OUTD   32
#define NEGF   (-3.4028234663852886e38f)

// ---------------- static scratch (no runtime allocation allowed) ----------------
__device__ float g_dec [NTOK * DMODEL];
__device__ float g_qb  [NTOK * DMODEL];
__device__ float g_kb  [NTOK * DMODEL];
__device__ float g_vb  [NTOK * DMODEL];
__device__ float g_tmp2[NTOK * DMODEL];
__device__ float g_ff  [NTOK * FFDIM];
__device__ float g_keys[NTOK * DMODEL];
__device__ float g_sc  [(size_t)64 * SEQ * SEQ];          // 256 MB attention scores
__device__ float g_vs  [(size_t)NTOK * NSLOTS * OUTD];    // 512 MB Vs

// ---------------- generic tiled SGEMM: C = A[M,K] @ B[K,N] (+bias) (+relu) ------
// requires M%128==0, N%128==0, K%16==0 (true for all call sites)
__global__ void sgemm_kernel(const float* __restrict__ A, const float* __restrict__ B,
                             const float* __restrict__ bias, float* __restrict__ C,
                             int M, int N, int K, int relu)
{
    __shared__ float As[16][128];
    __shared__ float Bs[16][128];
    const int tid = threadIdx.x;
    const int tx = tid & 15, ty = tid >> 4;
    const long brow = (long)blockIdx.y * 128;
    const long bcol = (long)blockIdx.x * 128;

    float acc[8][8];
#pragma unroll
    for (int i = 0; i < 8; i++)
#pragma unroll
        for (int j = 0; j < 8; j++) acc[i][j] = 0.f;

    for (int kt = 0; kt < K; kt += 16) {
#pragma unroll
        for (int i = 0; i < 2; i++) {
            int v = tid + i * 256;           // 512 float4 of A tile
            int r = v >> 2, c4 = v & 3;
            float4 av = *(const float4*)(A + (brow + r) * (long)K + kt + c4 * 4);
            As[c4 * 4 + 0][r] = av.x; As[c4 * 4 + 1][r] = av.y;
            As[c4 * 4 + 2][r] = av.z; As[c4 * 4 + 3][r] = av.w;
        }
#pragma unroll
        for (int i = 0; i < 2; i++) {
            int v = tid + i * 256;           // 512 float4 of B tile
            int r = v >> 5, c4 = v & 31;
            *(float4*)&Bs[r][c4 * 4] =
                *(const float4*)(B + (long)(kt + r) * N + bcol + c4 * 4);
        }
        __syncthreads();
#pragma unroll
        for (int k = 0; k < 16; k++) {
            float a[8], b[8];
            float4 t0 = *(float4*)&As[k][ty * 8];
            float4 t1 = *(float4*)&As[k][ty * 8 + 4];
            a[0]=t0.x; a[1]=t0.y; a[2]=t0.z; a[3]=t0.w;
            a[4]=t1.x; a[5]=t1.y; a[6]=t1.z; a[7]=t1.w;
            float4 u0 = *(float4*)&Bs[k][tx * 8];
            float4 u1 = *(float4*)&Bs[k][tx * 8 + 4];
            b[0]=u0.x; b[1]=u0.y; b[2]=u0.z; b[3]=u0.w;
            b[4]=u1.x; b[5]=u1.y; b[6]=u1.z; b[7]=u1.w;
#pragma unroll
            for (int i = 0; i < 8; i++)
#pragma unroll
                for (int j = 0; j < 8; j++) acc[i][j] += a[i] * b[j];
        }
        __syncthreads();
    }
#pragma unroll
    for (int i = 0; i < 8; i++) {
        long row = brow + ty * 8 + i;
#pragma unroll
        for (int j = 0; j < 8; j += 4) {
            long col = bcol + tx * 8 + j;
            float4 o;
            o.x = acc[i][j+0]; o.y = acc[i][j+1]; o.z = acc[i][j+2]; o.w = acc[i][j+3];
            if (bias) {
                o.x += bias[col+0]; o.y += bias[col+1];
                o.z += bias[col+2]; o.w += bias[col+3];
            }
            if (relu) {
                o.x = fmaxf(o.x, 0.f); o.y = fmaxf(o.y, 0.f);
                o.z = fmaxf(o.z, 0.f); o.w = fmaxf(o.w, 0.f);
            }
            *(float4*)(C + row * (long)N + col) = o;
        }
    }
}

// ---------------- causal attention scores: S[bh,q,k] = (q.k)/8 or NEG ----------
// grid (kt=16, qt=16, bh=64), block 256
__global__ void attn_scores_kernel(const float* __restrict__ Q, const float* __restrict__ K,
                                   float* __restrict__ S)
{
    const int kt = blockIdx.x, qt = blockIdx.y, bh = blockIdx.z;
    const int b = bh >> 3, h = bh & 7;
    const int tid = threadIdx.x;
    const size_t sbase = (size_t)bh * SEQ * SEQ;

    if (kt > qt) {                                   // fully masked tile
#pragma unroll
        for (int i = 0; i < 16; i++) {
            int v = tid + i * 256;                    // 4096 elems
            int r = v >> 6, c = v & 63;
            S[sbase + (size_t)(qt * 64 + r) * SEQ + kt * 64 + c] = NEGF;
        }
        return;
    }

    __shared__ float Qst[64][68];   // [d][row]
    __shared__ float Kst[64][68];   // [d][row]
#pragma unroll
    for (int i = 0; i < 4; i++) {
        int v = tid + i * 256;                        // 1024 float4
        int r = v >> 4, c4 = v & 15;
        float4 qv = *(const float4*)(Q + ((size_t)(b * SEQ + qt * 64 + r) * DMODEL) + h * HD + c4 * 4);
        Qst[c4*4+0][r]=qv.x; Qst[c4*4+1][r]=qv.y; Qst[c4*4+2][r]=qv.z; Qst[c4*4+3][r]=qv.w;
        float4 kv = *(const float4*)(K + ((size_t)(b * SEQ + kt * 64 + r) * DMODEL) + h * HD + c4 * 4);
        Kst[c4*4+0][r]=kv.x; Kst[c4*4+1][r]=kv.y; Kst[c4*4+2][r]=kv.z; Kst[c4*4+3][r]=kv.w;
    }
    __syncthreads();

    const int tx = tid & 15, ty = tid >> 4;
    float acc[4][4] = {};
#pragma unroll
    for (int d = 0; d < 64; d++) {
        float4 q4 = *(float4*)&Qst[d][ty * 4];
        float4 k4 = *(float4*)&Kst[d][tx * 4];
        float qa[4] = {q4.x, q4.y, q4.z, q4.w};
        float ka[4] = {k4.x, k4.y, k4.z, k4.w};
#pragma unroll
        for (int i = 0; i < 4; i++)
#pragma unroll
            for (int j = 0; j < 4; j++) acc[i][j] += qa[i] * ka[j];
    }
#pragma unroll
    for (int i = 0; i < 4; i++) {
        int q = qt * 64 + ty * 4 + i;
#pragma unroll
        for (int j = 0; j < 4; j++) {
            int kc = kt * 64 + tx * 4 + j;
            S[sbase + (size_t)q * SEQ + kc] = (kc <= q) ? acc[i][j] * 0.125f : NEGF;
        }
    }
}

// ---------------- row softmax (ncols = 512 or 1024), block 256 -----------------
__global__ void softmax_kernel(const float* __restrict__ src, float* __restrict__ dst, int ncols)
{
    const int row = blockIdx.x;
    const int tid = threadIdx.x;
    const int warp = tid >> 5, lane = tid & 31;
    const float* p = src + (size_t)row * ncols;
    const int c = ncols >> 8;                     // 2 or 4 per thread
    float v[4];
    float m = -INFINITY;
    for (int i = 0; i < c; i++) { v[i] = p[tid + i * 256]; m = fmaxf(m, v[i]); }
#pragma unroll
    for (int o = 16; o > 0; o >>= 1) m = fmaxf(m, __shfl_xor_sync(~0u, m, o));
    __shared__ float smax[8], ssum[8];
    if (lane == 0) smax[warp] = m;
    __syncthreads();
    m = smax[0];
#pragma unroll
    for (int w = 1; w < 8; w++) m = fmaxf(m, smax[w]);
    float sum = 0.f;
    for (int i = 0; i < c; i++) { v[i] = expf(v[i] - m); sum += v[i]; }
#pragma unroll
    for (int o = 16; o > 0; o >>= 1) sum += __shfl_xor_sync(~0u, sum, o);
    if (lane == 0) ssum[warp] = sum;
    __syncthreads();
    sum = ssum[0];
#pragma unroll
    for (int w = 1; w < 8; w++) sum += ssum[w];
    float inv = 1.f / sum;
    float* q = dst + (size_t)row * ncols;
    for (int i = 0; i < c; i++) q[tid + i * 256] = v[i] * inv;
}

// ---------------- attention output: O = P @ V, per (b,h), causal chunk skip ----
// grid (1, qt=16, bh=64), block 256
__global__ void attn_out_kernel(const float* __restrict__ P, const float* __restrict__ V,
                                float* __restrict__ O)
{
    const int qt = blockIdx.y, bh = blockIdx.z;
    const int b = bh >> 3, h = bh & 7;
    const int tid = threadIdx.x;
    const size_t pbase = (size_t)bh * SEQ * SEQ;

    __shared__ float Pst[32][68];   // [kk][qrow]
    __shared__ float Vs2[32][68];   // [kk][d]
    const int tx = tid & 15, ty = tid >> 4;
    float acc[4][4] = {};

    const int nch = (qt + 1) * 2;                 // 32-wide k-chunks needed
    for (int kc = 0; kc < nch; kc++) {
#pragma unroll
        for (int i = 0; i < 2; i++) {
            int v = tid + i * 256;                // P tile: 64x32 = 512 float4
            int r = v >> 3, c4 = v & 7;
            float4 pv = *(const float4*)(P + pbase + (size_t)(qt * 64 + r) * SEQ + kc * 32 + c4 * 4);
            Pst[c4*4+0][r]=pv.x; Pst[c4*4+1][r]=pv.y; Pst[c4*4+2][r]=pv.z; Pst[c4*4+3][r]=pv.w;
            int v2 = tid + i * 256;               // V tile: 32x64 = 512 float4
            int r2 = v2 >> 4, c42 = v2 & 15;
            *(float4*)&Vs2[r2][c42 * 4] =
                *(const float4*)(V + ((size_t)(b * SEQ + kc * 32 + r2) * DMODEL) + h * HD + c42 * 4);
        }
        __syncthreads();
#pragma unroll
        for (int kk = 0; kk < 32; kk++) {
            float4 p4 = *(float4*)&Pst[kk][ty * 4];
            float4 v4 = *(float4*)&Vs2[kk][tx * 4];
            float pa[4] = {p4.x, p4.y, p4.z, p4.w};
            float va[4] = {v4.x, v4.y, v4.z, v4.w};
#pragma unroll
            for (int i = 0; i < 4; i++)
#pragma unroll
                for (int j = 0; j < 4; j++) acc[i][j] += pa[i] * va[j];
        }
        __syncthreads();
    }
#pragma unroll
    for (int i = 0; i < 4; i++) {
        int q = qt * 64 + ty * 4 + i;
#pragma unroll
        for (int j = 0; j < 4; j++) {
            int d = tx * 4 + j;
            O[((size_t)(b * SEQ + q) * DMODEL) + h * HD + d] = acc[i][j];
        }
    }
}

// ---------------- residual + LayerNorm (D=512), block 128 ----------------------
__global__ void ln_kernel(const float* __restrict__ xin, const float* __restrict__ res,
                          const float* __restrict__ scale, const float* __restrict__ bias,
                          float* __restrict__ out)
{
    const int row = blockIdx.x;
    const int tid = threadIdx.x;           // 128 threads x float4 = 512
    float4 v = ((const float4*)(xin + (size_t)row * DMODEL))[tid];
    if (res) {
        float4 r = ((const float4*)(res + (size_t)row * DMODEL))[tid];
        v.x += r.x; v.y += r.y; v.z += r.z; v.w += r.w;
    }
    float s  = v.x + v.y + v.z + v.w;
    float sq = v.x * v.x + v.y * v.y + v.z * v.z + v.w * v.w;
#pragma unroll
    for (int o = 16; o > 0; o >>= 1) {
        s  += __shfl_xor_sync(~0u, s,  o);
        sq += __shfl_xor_sync(~0u, sq, o);
    }
    __shared__ float ss[4], sqs[4];
    const int warp = tid >> 5, lane = tid & 31;
    if (lane == 0) { ss[warp] = s; sqs[warp] = sq; }
    __syncthreads();
    float S  = ss[0]  + ss[1]  + ss[2]  + ss[3];
    float SQ = sqs[0] + sqs[1] + sqs[2] + sqs[3];
    float mean = S * (1.f / DMODEL);
    float var  = SQ * (1.f / DMODEL) - mean * mean;
    float rs   = rsqrtf(var + 1e-6f);
    float4 sc4 = ((const float4*)scale)[tid];
    float4 bi4 = ((const float4*)bias)[tid];
    float4 o;
    o.x = (v.x - mean) * rs * sc4.x + bi4.x;
    o.y = (v.y - mean) * rs * sc4.y + bi4.y;
    o.z = (v.z - mean) * rs * sc4.z + bi4.z;
    o.w = (v.w - mean) * rs * sc4.w + bi4.w;
    ((float4*)(out + (size_t)row * DMODEL))[tid] = o;
}

// ---------------- cosine-score argmax + gather: one block per token ------------
__global__ void score_argmax_kernel(const float* __restrict__ Vs, const float* __restrict__ x,
                                    const float* __restrict__ Ss, float* __restrict__ vout,
                                    float* __restrict__ sout)
{
    const int n = blockIdx.x;
    const int tid = threadIdx.x;
    const int warp = tid >> 5, lane = tid & 31;
    __shared__ float xs[32];
    __shared__ float wbest[8];
    __shared__ int   widx[8];
    if (tid < 32) xs[tid] = x[(size_t)n * OUTD + tid];
    __syncthreads();
    const float xv = xs[lane];
    const float* vrow = Vs + (size_t)n * NSLOTS * OUTD;

    float best = -INFINITY;
    int   bidx = 0;
    for (int k = warp; k < NSLOTS; k += 8) {
        float v = vrow[k * OUTD + lane];
        float d = v * xv;
        float s = v * v;
#pragma unroll
        for (int o = 16; o > 0; o >>= 1) {
            d += __shfl_xor_sync(~0u, d, o);
            s += __shfl_xor_sync(~0u, s, o);
        }
        float sc = d / sqrtf(s);
        if (sc > best) { best = sc; bidx = k; }   // strict > keeps first max per warp
    }
    if (lane == 0) { wbest[warp] = best; widx[warp] = bidx; }
    __syncthreads();
    if (tid == 0) {
        float b = wbest[0]; int bi = widx[0];
        for (int w = 1; w < 8; w++) {
            if (wbest[w] > b || (wbest[w] == b && widx[w] < bi)) { b = wbest[w]; bi = widx[w]; }
        }
        widx[0] = bi;
    }
    __syncthreads();
    const int idx = widx[0];
    if (tid < 32) vout[(size_t)n * OUTD + tid] = vrow[idx * OUTD + tid];
    if (tid == 0) sout[n] = Ss[(size_t)n * NSLOTS + idx];
}

// ---------------- launch --------------------------------------------------------
extern "C" void kernel_launch(void* const* d_in, const int* in_sizes, int n_in,
                              void* d_out, int out_size)
{
    const float* s_in  = (const float*)d_in[0];
    const float* x_in  = (const float*)d_in[1];
    const float* t_in  = (const float*)d_in[2];
    const float* Wq    = (const float*)d_in[3];
    const float* Wk    = (const float*)d_in[4];
    const float* Wv    = (const float*)d_in[5];
    const float* Wo    = (const float*)d_in[6];
    // d_in[7] cWq, d_in[8] cWk: numerically dead (eye-masked cross attention)
    const float* cWv   = (const float*)d_in[9];
    const float* cWo   = (const float*)d_in[10];
    const float* ln1_s = (const float*)d_in[11];
    const float* ln1_b = (const float*)d_in[12];
    const float* ln2_s = (const float*)d_in[13];
    const float* ln2_b = (const float*)d_in[14];
    const float* ln3_s = (const float*)d_in[15];
    const float* ln3_b = (const float*)d_in[16];
    const float* W1    = (const float*)d_in[17];
    const float* b1    = (const float*)d_in[18];
    const float* W2    = (const float*)d_in[19];
    const float* b2    = (const float*)d_in[20];
    const float* lnf_s = (const float*)d_in[21];
    const float* lnf_b = (const float*)d_in[22];
    const float* Wout  = (const float*)d_in[23];
    const float* bout  = (const float*)d_in[24];
    const float* W_vs  = (const float*)d_in[25];
    const float* b_vs  = (const float*)d_in[26];
    const float* W_ss  = (const float*)d_in[27];
    const float* b_ss  = (const float*)d_in[28];
    float* out = (float*)d_out;

    float *dec, *qb, *kb, *vb, *tmp2, *ff, *keys, *sc, *vs;
    cudaGetSymbolAddress((void**)&dec,  g_dec);
    cudaGetSymbolAddress((void**)&qb,   g_qb);
    cudaGetSymbolAddress((void**)&kb,   g_kb);
    cudaGetSymbolAddress((void**)&vb,   g_vb);
    cudaGetSymbolAddress((void**)&tmp2, g_tmp2);
    cudaGetSymbolAddress((void**)&ff,   g_ff);
    cudaGetSymbolAddress((void**)&keys, g_keys);
    cudaGetSymbolAddress((void**)&sc,   g_sc);
    cudaGetSymbolAddress((void**)&vs,   g_vs);

    cudaMemcpyAsync(dec, s_in, sizeof(float) * NTOK * DMODEL, cudaMemcpyDeviceToDevice);

    const dim3 g512(DMODEL / 128, NTOK / 128);     // (4, 64)
    const dim3 gff (FFDIM  / 128, NTOK / 128);     // (16, 64)

    for (int l = 0; l < 2; l++) {
        const size_t wo = (size_t)l * DMODEL * DMODEL;
        // ---- causal self-attention ----
        sgemm_kernel<<<g512, 256>>>(dec, Wq + wo, nullptr, qb, NTOK, DMODEL, DMODEL, 0);
        sgemm_kernel<<<g512, 256>>>(dec, Wk + wo, nullptr, kb, NTOK, DMODEL, DMODEL, 0);
        sgemm_kernel<<<g512, 256>>>(dec, Wv + wo, nullptr, vb, NTOK, DMODEL, DMODEL, 0);
        attn_scores_kernel<<<dim3(16, 16, 64), 256>>>(qb, kb, sc);
        softmax_kernel<<<64 * SEQ, 256>>>(sc, sc, SEQ);
        attn_out_kernel<<<dim3(1, 16, 64), 256>>>(sc, vb, qb);   // reuse qb as attn out
        sgemm_kernel<<<g512, 256>>>(qb, Wo + wo, nullptr, tmp2, NTOK, DMODEL, DMODEL, 0);
        ln_kernel<<<NTOK, 128>>>(dec, tmp2, ln1_s + l * DMODEL, ln1_b + l * DMODEL, dec);
        // ---- cross-attention (eye mask => o = t @ cWv) ----
        sgemm_kernel<<<g512, 256>>>(t_in, cWv + wo, nullptr, qb, NTOK, DMODEL, DMODEL, 0);
        sgemm_kernel<<<g512, 256>>>(qb, cWo + wo, nullptr, tmp2, NTOK, DMODEL, DMODEL, 0);
        ln_kernel<<<NTOK, 128>>>(dec, tmp2, ln2_s + l * DMODEL, ln2_b + l * DMODEL, dec);
        // ---- FFN ----
        sgemm_kernel<<<gff, 256>>>(dec, W1 + (size_t)l * DMODEL * FFDIM, b1 + (size_t)l * FFDIM,
                                   ff, NTOK, FFDIM, DMODEL, 1);
        sgemm_kernel<<<g512, 256>>>(ff, W2 + (size_t)l * FFDIM * DMODEL, b2 + (size_t)l * DMODEL,
                                    tmp2, NTOK, DMODEL, FFDIM, 0);
        ln_kernel<<<NTOK, 128>>>(dec, tmp2, ln3_s + l * DMODEL, ln3_b + l * DMODEL, dec);
    }

    // ---- final head ----
    ln_kernel<<<NTOK, 128>>>(dec, nullptr, lnf_s, lnf_b, tmp2);
    sgemm_kernel<<<g512, 256>>>(tmp2, Wout, bout, qb, NTOK, DMODEL, DMODEL, 0);   // logits
    softmax_kernel<<<NTOK, 256>>>(qb, keys, DMODEL);

    float* out_v  = out;                          // [8192, 32]
    float* out_s  = out + 262144;                 // [8192]
    float* out_ss = out + 262144 + 8192;          // [8192, 512]

    sgemm_kernel<<<g512, 256>>>(keys, W_ss, b_ss, out_ss, NTOK, NSLOTS, DMODEL, 0);
    sgemm_kernel<<<dim3(NSLOTS * OUTD / 128, NTOK / 128), 256>>>(
        keys, W_vs, b_vs, vs, NTOK, NSLOTS * OUTD, DMODEL, 0);
    score_argmax_kernel<<<NTOK, 256>>>(vs, x_in, out_ss, out_v, out_s);
}

// round 3
// speedup vs baseline: 1.8762x; 1.8762x over previous
#include <cuda_runtime.h>
#include <cuda_bf16.h>
#include <math.h>
#include <stdint.h>

#define NTOK   8192
#define DMODEL 512
#define HEADS  8
#define HD     64
#define SEQ    1024
#define FFDIM  2048
#define NSLOTS 512
#define OUTD   32
#define NEGF   (-3.4028234663852886e38f)

// ---------------- static scratch ----------------
__device__ float g_dec [NTOK * DMODEL];
__device__ float g_qb  [NTOK * DMODEL];
__device__ float g_kb  [NTOK * DMODEL];
__device__ float g_vb  [NTOK * DMODEL];
__device__ float g_tmp2[NTOK * DMODEL];
__device__ float g_ff  [NTOK * FFDIM];
__device__ float g_keys[NTOK * DMODEL];
__device__ float g_sc  [(size_t)64 * SEQ * SEQ];
__device__ float g_vs  [(size_t)NTOK * NSLOTS * OUTD];
__device__ __nv_bfloat16 g_bthi[8388608];   // transposed weight hi [N,K]
__device__ __nv_bfloat16 g_btlo[8388608];   // transposed weight lo [N,K]

__device__ __forceinline__ uint32_t smem_u32(const void* p) {
    uint32_t a;
    asm("{ .reg .u64 t; cvta.to.shared.u64 t, %1; cvt.u32.u64 %0, t; }" : "=r"(a) : "l"(p));
    return a;
}
__device__ __forceinline__ uint32_t pack2(__nv_bfloat16 a, __nv_bfloat16 b) {
    return (uint32_t)__bfloat16_as_ushort(a) | ((uint32_t)__bfloat16_as_ushort(b) << 16);
}

#define LDMX4(r0, r1, r2, r3, addr) \
    asm volatile("ldmatrix.sync.aligned.m8n8.x4.shared.b16 {%0,%1,%2,%3}, [%4];" \
        : "=r"(r0), "=r"(r1), "=r"(r2), "=r"(r3) : "r"(addr))

#define MMA_BF16(c, a, b) \
    asm volatile("mma.sync.aligned.m16n8k16.row.col.f32.bf16.bf16.f32 " \
        "{%0,%1,%2,%3}, {%4,%5,%6,%7}, {%8,%9}, {%0,%1,%2,%3};" \
        : "+f"((c)[0]), "+f"((c)[1]), "+f"((c)[2]), "+f"((c)[3]) \
        : "r"((a)[0]), "r"((a)[1]), "r"((a)[2]), "r"((a)[3]), "r"((b)[0]), "r"((b)[1]))

#define LDP 72                         // padded bf16 row stride (144B: conflict-free)
#define TILE_ELEMS (128 * LDP)
#define GEMM_SMEM (4 * TILE_ELEMS * 2) // 73728 B

// ============ split-bf16 HMMA GEMM: C[M,N] = A[M,K] @ Bt[N,K]^T (+bias)(+relu) ===
// A fp32 row-major; Bt hi/lo bf16 row-major [N,K]. 3-pass: AhBh + AhBl + AlBh.
__global__ __launch_bounds__(256, 1)
void gemm_mma_kernel(const float* __restrict__ A,
                     const __nv_bfloat16* __restrict__ Bhi,
                     const __nv_bfloat16* __restrict__ Blo,
                     const float* __restrict__ bias, float* __restrict__ C,
                     int M, int N, int K, int relu)
{
    extern __shared__ char smem[];
    __nv_bfloat16* sAh = (__nv_bfloat16*)smem;
    __nv_bfloat16* sAl = sAh + TILE_ELEMS;
    __nv_bfloat16* sBh = sAl + TILE_ELEMS;
    __nv_bfloat16* sBl = sBh + TILE_ELEMS;

    const int tid  = threadIdx.x;
    const int lane = tid & 31;
    const int wid  = tid >> 5;
    const int wm   = wid >> 2;          // 0..1 -> 64-row warp tile
    const int wn   = wid & 3;           // 0..3 -> 32-col warp tile
    const size_t brow = (size_t)blockIdx.y * 128;
    const size_t bcol = (size_t)blockIdx.x * 128;

    // global-load thread mapping
    const int a_kg = tid & 15, a_r0 = tid >> 4;     // A: float4, 16 rows/iter
    const int b_kg = tid & 7,  b_r0 = tid >> 3;     // B: uint4,  32 rows/iter

    float4 aReg[8];
    uint4  bhReg[4], blReg[4];

    const int NP = K >> 6;
    // prologue: load panel 0
    {
        const float* ap = A + (brow + a_r0) * K + a_kg * 4;
#pragma unroll
        for (int it = 0; it < 8; it++) aReg[it] = *(const float4*)(ap + (size_t)(it * 16) * K);
        const __nv_bfloat16* bh = Bhi + (bcol + b_r0) * K + b_kg * 8;
        const __nv_bfloat16* bl = Blo + (bcol + b_r0) * K + b_kg * 8;
#pragma unroll
        for (int it = 0; it < 4; it++) {
            bhReg[it] = *(const uint4*)(bh + (size_t)(it * 32) * K);
            blReg[it] = *(const uint4*)(bl + (size_t)(it * 32) * K);
        }
    }

    float acc[4][4][4];
#pragma unroll
    for (int i = 0; i < 4; i++)
#pragma unroll
        for (int j = 0; j < 4; j++)
#pragma unroll
            for (int c = 0; c < 4; c++) acc[i][j][c] = 0.f;

    // ldmatrix lane addressing
    const int lm_r = (lane & 7) + ((lane >> 3) & 1) * 8;   // A: row within 16
    const int lm_c = ((lane >> 4) & 1) * 8;                // A: k-half
    const int lb_r = (lane & 7) + ((lane >> 4) & 1) * 8;   // B: n within 16
    const int lb_c = ((lane >> 3) & 1) * 8;                // B: k-half

    for (int p = 0; p < NP; p++) {
        if (p > 0) __syncthreads();
        // stage regs -> smem (A converted to hi/lo)
#pragma unroll
        for (int it = 0; it < 8; it++) {
            float4 v = aReg[it];
            __nv_bfloat16 hx = __float2bfloat16(v.x), hy = __float2bfloat16(v.y);
            __nv_bfloat16 hz = __float2bfloat16(v.z), hw = __float2bfloat16(v.w);
            __nv_bfloat16 lx = __float2bfloat16(v.x - __bfloat162float(hx));
            __nv_bfloat16 ly = __float2bfloat16(v.y - __bfloat162float(hy));
            __nv_bfloat16 lz = __float2bfloat16(v.z - __bfloat162float(hz));
            __nv_bfloat16 lw = __float2bfloat16(v.w - __bfloat162float(hw));
            const int off = (a_r0 + it * 16) * LDP + a_kg * 4;
            *(uint2*)(sAh + off) = make_uint2(pack2(hx, hy), pack2(hz, hw));
            *(uint2*)(sAl + off) = make_uint2(pack2(lx, ly), pack2(lz, lw));
        }
#pragma unroll
        for (int it = 0; it < 4; it++) {
            const int off = (b_r0 + it * 32) * LDP + b_kg * 8;
            *(uint4*)(sBh + off) = bhReg[it];
            *(uint4*)(sBl + off) = blReg[it];
        }
        __syncthreads();

        // prefetch next panel into regs
        if (p + 1 < NP) {
            const float* ap = A + (brow + a_r0) * K + (size_t)(p + 1) * 64 + a_kg * 4;
#pragma unroll
            for (int it = 0; it < 8; it++) aReg[it] = *(const float4*)(ap + (size_t)(it * 16) * K);
            const __nv_bfloat16* bh = Bhi + (bcol + b_r0) * K + (size_t)(p + 1) * 64 + b_kg * 8;
            const __nv_bfloat16* bl = Blo + (bcol + b_r0) * K + (size_t)(p + 1) * 64 + b_kg * 8;
#pragma unroll
            for (int it = 0; it < 4; it++) {
                bhReg[it] = *(const uint4*)(bh + (size_t)(it * 32) * K);
                blReg[it] = *(const uint4*)(bl + (size_t)(it * 32) * K);
            }
        }

        // compute 4 k-steps of 16
#pragma unroll
        for (int ks = 0; ks < 4; ks++) {
            const int k0 = ks * 16;
            uint32_t Ah[4][4], Al[4][4], Bh[4][2], Bl[4][2];
#pragma unroll
            for (int mi = 0; mi < 4; mi++) {
                const int r = wm * 64 + mi * 16 + lm_r;
                const uint32_t ah = smem_u32(sAh + r * LDP + k0 + lm_c);
                LDMX4(Ah[mi][0], Ah[mi][1], Ah[mi][2], Ah[mi][3], ah);
                const uint32_t al = smem_u32(sAl + r * LDP + k0 + lm_c);
                LDMX4(Al[mi][0], Al[mi][1], Al[mi][2], Al[mi][3], al);
            }
#pragma unroll
            for (int nio = 0; nio < 2; nio++) {
                const int r = wn * 32 + nio * 16 + lb_r;
                const uint32_t bh = smem_u32(sBh + r * LDP + k0 + lb_c);
                LDMX4(Bh[2*nio][0], Bh[2*nio][1], Bh[2*nio+1][0], Bh[2*nio+1][1], bh);
                const uint32_t bl = smem_u32(sBl + r * LDP + k0 + lb_c);
                LDMX4(Bl[2*nio][0], Bl[2*nio][1], Bl[2*nio+1][0], Bl[2*nio+1][1], bl);
            }
#pragma unroll
            for (int mi = 0; mi < 4; mi++)
#pragma unroll
                for (int ni = 0; ni < 4; ni++) {
                    MMA_BF16(acc[mi][ni], Ah[mi], Bh[ni]);
                    MMA_BF16(acc[mi][ni], Ah[mi], Bl[ni]);
                    MMA_BF16(acc[mi][ni], Al[mi], Bh[ni]);
                }
        }
    }

    // epilogue: fragment -> global, + bias + relu
    const int g = lane >> 2, t = lane & 3;
#pragma unroll
    for (int mi = 0; mi < 4; mi++) {
        const size_t rm = brow + wm * 64 + mi * 16 + g;
#pragma unroll
        for (int ni = 0; ni < 4; ni++) {
            const size_t cn = bcol + wn * 32 + ni * 8 + 2 * t;
            float b0 = 0.f, b1 = 0.f;
            if (bias) { b0 = bias[cn]; b1 = bias[cn + 1]; }
            float2 o0 = make_float2(acc[mi][ni][0] + b0, acc[mi][ni][1] + b1);
            float2 o1 = make_float2(acc[mi][ni][2] + b0, acc[mi][ni][3] + b1);
            if (relu) {
                o0.x = fmaxf(o0.x, 0.f); o0.y = fmaxf(o0.y, 0.f);
                o1.x = fmaxf(o1.x, 0.f); o1.y = fmaxf(o1.y, 0.f);
            }
            *(float2*)(C + rm * N + cn)       = o0;
            *(float2*)(C + (rm + 8) * N + cn) = o1;
        }
    }
}

// ============ transpose + split-convert: W[K,N] fp32 -> hi/lo [N,K] bf16 ======
__global__ void transpose_convert_kernel(const float* __restrict__ W,
                                         __nv_bfloat16* __restrict__ Hi,
                                         __nv_bfloat16* __restrict__ Lo, int K, int N)
{
    __shared__ float t[32][33];
    const int k0 = blockIdx.y * 32, n0 = blockIdx.x * 32;
    const int tx = threadIdx.x & 31, ty = threadIdx.x >> 5;
#pragma unroll
    for (int j = 0; j < 32; j += 8)
        t[ty + j][tx] = W[(size_t)(k0 + ty + j) * N + n0 + tx];
    __syncthreads();
#pragma unroll
    for (int j = 0; j < 32; j += 8) {
        float v = t[tx][ty + j];
        __nv_bfloat16 h = __float2bfloat16(v);
        __nv_bfloat16 l = __float2bfloat16(v - __bfloat162float(h));
        Hi[(size_t)(n0 + ty + j) * K + k0 + tx] = h;
        Lo[(size_t)(n0 + ty + j) * K + k0 + tx] = l;
    }
}

// ---------------- causal attention scores (fp32) ----------------
__global__ void attn_scores_kernel(const float* __restrict__ Q, const float* __restrict__ K,
                                   float* __restrict__ S)
{
    const int kt = blockIdx.x, qt = blockIdx.y, bh = blockIdx.z;
    const int b = bh >> 3, h = bh & 7;
    const int tid = threadIdx.x;
    const size_t sbase = (size_t)bh * SEQ * SEQ;

    if (kt > qt) {
#pragma unroll
        for (int i = 0; i < 16; i++) {
            int v = tid + i * 256;
            int r = v >> 6, c = v & 63;
            S[sbase + (size_t)(qt * 64 + r) * SEQ + kt * 64 + c] = NEGF;
        }
        return;
    }
    __shared__ float Qst[64][68];
    __shared__ float Kst[64][68];
#pragma unroll
    for (int i = 0; i < 4; i++) {
        int v = tid + i * 256;
        int r = v >> 4, c4 = v & 15;
        float4 qv = *(const float4*)(Q + ((size_t)(b * SEQ + qt * 64 + r) * DMODEL) + h * HD + c4 * 4);
        Qst[c4*4+0][r]=qv.x; Qst[c4*4+1][r]=qv.y; Qst[c4*4+2][r]=qv.z; Qst[c4*4+3][r]=qv.w;
        float4 kv = *(const float4*)(K + ((size_t)(b * SEQ + kt * 64 + r) * DMODEL) + h * HD + c4 * 4);
        Kst[c4*4+0][r]=kv.x; Kst[c4*4+1][r]=kv.y; Kst[c4*4+2][r]=kv.z; Kst[c4*4+3][r]=kv.w;
    }
    __syncthreads();
    const int tx = tid & 15, ty = tid >> 4;
    float acc[4][4] = {};
#pragma unroll
    for (int d = 0; d < 64; d++) {
        float4 q4 = *(float4*)&Qst[d][ty * 4];
        float4 k4 = *(float4*)&Kst[d][tx * 4];
        float qa[4] = {q4.x, q4.y, q4.z, q4.w};
        float ka[4] = {k4.x, k4.y, k4.z, k4.w};
#pragma unroll
        for (int i = 0; i < 4; i++)
#pragma unroll
            for (int j = 0; j < 4; j++) acc[i][j] += qa[i] * ka[j];
    }
#pragma unroll
    for (int i = 0; i < 4; i++) {
        int q = qt * 64 + ty * 4 + i;
#pragma unroll
        for (int j = 0; j < 4; j++) {
            int kc = kt * 64 + tx * 4 + j;
            S[sbase + (size_t)q * SEQ + kc] = (kc <= q) ? acc[i][j] * 0.125f : NEGF;
        }
    }
}

// ---------------- row softmax ----------------
__global__ void softmax_kernel(const float* __restrict__ src, float* __restrict__ dst, int ncols)
{
    const int row = blockIdx.x;
    const int tid = threadIdx.x;
    const int warp = tid >> 5, lane = tid & 31;
    const float* p = src + (size_t)row * ncols;
    const int c = ncols >> 8;
    float v[4];
    float m = -INFINITY;
    for (int i = 0; i < c; i++) { v[i] = p[tid + i * 256]; m = fmaxf(m, v[i]); }
#pragma unroll
    for (int o = 16; o > 0; o >>= 1) m = fmaxf(m, __shfl_xor_sync(~0u, m, o));
    __shared__ float smax[8], ssum[8];
    if (lane == 0) smax[warp] = m;
    __syncthreads();
    m = smax[0];
#pragma unroll
    for (int w = 1; w < 8; w++) m = fmaxf(m, smax[w]);
    float sum = 0.f;
    for (int i = 0; i < c; i++) { v[i] = expf(v[i] - m); sum += v[i]; }
#pragma unroll
    for (int o = 16; o > 0; o >>= 1) sum += __shfl_xor_sync(~0u, sum, o);
    if (lane == 0) ssum[warp] = sum;
    __syncthreads();
    sum = ssum[0];
#pragma unroll
    for (int w = 1; w < 8; w++) sum += ssum[w];
    float inv = 1.f / sum;
    float* q = dst + (size_t)row * ncols;
    for (int i = 0; i < c; i++) q[tid + i * 256] = v[i] * inv;
}

// ---------------- attention output (fp32) ----------------
__global__ void attn_out_kernel(const float* __restrict__ P, const float* __restrict__ V,
                                float* __restrict__ O)
{
    const int qt = blockIdx.y, bh = blockIdx.z;
    const int b = bh >> 3, h = bh & 7;
    const int tid = threadIdx.x;
    const size_t pbase = (size_t)bh * SEQ * SEQ;

    __shared__ float Pst[32][68];
    __shared__ float Vs2[32][68];
    const int tx = tid & 15, ty = tid >> 4;
    float acc[4][4] = {};

    const int nch = (qt + 1) * 2;
    for (int kc = 0; kc < nch; kc++) {
#pragma unroll
        for (int i = 0; i < 2; i++) {
            int v = tid + i * 256;
            int r = v >> 3, c4 = v & 7;
            float4 pv = *(const float4*)(P + pbase + (size_t)(qt * 64 + r) * SEQ + kc * 32 + c4 * 4);
            Pst[c4*4+0][r]=pv.x; Pst[c4*4+1][r]=pv.y; Pst[c4*4+2][r]=pv.z; Pst[c4*4+3][r]=pv.w;
            int r2 = v >> 4, c42 = v & 15;
            *(float4*)&Vs2[r2][c42 * 4] =
                *(const float4*)(V + ((size_t)(b * SEQ + kc * 32 + r2) * DMODEL) + h * HD + c42 * 4);
        }
        __syncthreads();
#pragma unroll
        for (int kk = 0; kk < 32; kk++) {
            float4 p4 = *(float4*)&Pst[kk][ty * 4];
            float4 v4 = *(float4*)&Vs2[kk][tx * 4];
            float pa[4] = {p4.x, p4.y, p4.z, p4.w};
            float va[4] = {v4.x, v4.y, v4.z, v4.w};
#pragma unroll
            for (int i = 0; i < 4; i++)
#pragma unroll
                for (int j = 0; j < 4; j++) acc[i][j] += pa[i] * va[j];
        }
        __syncthreads();
    }
#pragma unroll
    for (int i = 0; i < 4; i++) {
        int q = qt * 64 + ty * 4 + i;
#pragma unroll
        for (int j = 0; j < 4; j++)
            O[((size_t)(b * SEQ + q) * DMODEL) + h * HD + tx * 4 + j] = acc[i][j];
    }
}

// ---------------- residual + LayerNorm ----------------
__global__ void ln_kernel(const float* __restrict__ xin, const float* __restrict__ res,
                          const float* __restrict__ scale, const float* __restrict__ bias,
                          float* __restrict__ out)
{
    const int row = blockIdx.x;
    const int tid = threadIdx.x;
    float4 v = ((const float4*)(xin + (size_t)row * DMODEL))[tid];
    if (res) {
        float4 r = ((const float4*)(res + (size_t)row * DMODEL))[tid];
        v.x += r.x; v.y += r.y; v.z += r.z; v.w += r.w;
    }
    float s  = v.x + v.y + v.z + v.w;
    float sq = v.x * v.x + v.y * v.y + v.z * v.z + v.w * v.w;
#pragma unroll
    for (int o = 16; o > 0; o >>= 1) {
        s  += __shfl_xor_sync(~0u, s,  o);
        sq += __shfl_xor_sync(~0u, sq, o);
    }
    __shared__ float ss[4], sqs[4];
    const int warp = tid >> 5, lane = tid & 31;
    if (lane == 0) { ss[warp] = s; sqs[warp] = sq; }
    __syncthreads();
    float S  = ss[0]  + ss[1]  + ss[2]  + ss[3];
    float SQ = sqs[0] + sqs[1] + sqs[2] + sqs[3];
    float mean = S * (1.f / DMODEL);
    float var  = SQ * (1.f / DMODEL) - mean * mean;
    float rs   = rsqrtf(var + 1e-6f);
    float4 sc4 = ((const float4*)scale)[tid];
    float4 bi4 = ((const float4*)bias)[tid];
    float4 o;
    o.x = (v.x - mean) * rs * sc4.x + bi4.x;
    o.y = (v.y - mean) * rs * sc4.y + bi4.y;
    o.z = (v.z - mean) * rs * sc4.z + bi4.z;
    o.w = (v.w - mean) * rs * sc4.w + bi4.w;
    ((float4*)(out + (size_t)row * DMODEL))[tid] = o;
}

// ---------------- cosine-score argmax + gather ----------------
__global__ void score_argmax_kernel(const float* __restrict__ Vs, const float* __restrict__ x,
                                    const float* __restrict__ Ss, float* __restrict__ vout,
                                    float* __restrict__ sout)
{
    const int n = blockIdx.x;
    const int tid = threadIdx.x;
    const int warp = tid >> 5, lane = tid & 31;
    __shared__ float xs[32];
    __shared__ float wbest[8];
    __shared__ int   widx[8];
    if (tid < 32) xs[tid] = x[(size_t)n * OUTD + tid];
    __syncthreads();
    const float xv = xs[lane];
    const float* vrow = Vs + (size_t)n * NSLOTS * OUTD;

    float best = -INFINITY;
    int   bidx = 0;
    for (int k = warp; k < NSLOTS; k += 8) {
        float v = vrow[k * OUTD + lane];
        float d = v * xv;
        float s = v * v;
#pragma unroll
        for (int o = 16; o > 0; o >>= 1) {
            d += __shfl_xor_sync(~0u, d, o);
            s += __shfl_xor_sync(~0u, s, o);
        }
        float sc = d / sqrtf(s);
        if (sc > best) { best = sc; bidx = k; }
    }
    if (lane == 0) { wbest[warp] = best; widx[warp] = bidx; }
    __syncthreads();
    if (tid == 0) {
        float b = wbest[0]; int bi = widx[0];
        for (int w = 1; w < 8; w++)
            if (wbest[w] > b || (wbest[w] == b && widx[w] < bi)) { b = wbest[w]; bi = widx[w]; }
        widx[0] = bi;
    }
    __syncthreads();
    const int idx = widx[0];
    if (tid < 32) vout[(size_t)n * OUTD + tid] = vrow[idx * OUTD + tid];
    if (tid == 0) sout[n] = Ss[(size_t)n * NSLOTS + idx];
}

// ---------------- host-side GEMM wrapper ----------------
static void tc_gemm(const float* A, const float* W, const float* bias, float* C,
                    int M, int N, int K, int relu,
                    __nv_bfloat16* bthi, __nv_bfloat16* btlo)
{
    transpose_convert_kernel<<<dim3(N / 32, K / 32), 256>>>(W, bthi, btlo, K, N);
    gemm_mma_kernel<<<dim3(N / 128, M / 128), 256, GEMM_SMEM>>>(A, bthi, btlo, bias, C, M, N, K, relu);
}

// ---------------- launch ----------------
extern "C" void kernel_launch(void* const* d_in, const int* in_sizes, int n_in,
                              void* d_out, int out_size)
{
    const float* s_in  = (const float*)d_in[0];
    const float* x_in  = (const float*)d_in[1];
    const float* t_in  = (const float*)d_in[2];
    const float* Wq    = (const float*)d_in[3];
    const float* Wk    = (const float*)d_in[4];
    const float* Wv    = (const float*)d_in[5];
    const float* Wo    = (const float*)d_in[6];
    const float* cWv   = (const float*)d_in[9];
    const float* cWo   = (const float*)d_in[10];
    const float* ln1_s = (const float*)d_in[11];
    const float* ln1_b = (const float*)d_in[12];
    const float* ln2_s = (const float*)d_in[13];
    const float* ln2_b = (const float*)d_in[14];
    const float* ln3_s = (const float*)d_in[15];
    const float* ln3_b = (const float*)d_in[16];
    const float* W1    = (const float*)d_in[17];
    const float* b1    = (const float*)d_in[18];
    const float* W2    = (const float*)d_in[19];
    const float* b2    = (const float*)d_in[20];
    const float* lnf_s = (const float*)d_in[21];
    const float* lnf_b = (const float*)d_in[22];
    const float* Wout  = (const float*)d_in[23];
    const float* bout  = (const float*)d_in[24];
    const float* W_vs  = (const float*)d_in[25];
    const float* b_vs  = (const float*)d_in[26];
    const float* W_ss  = (const float*)d_in[27];
    const float* b_ss  = (const float*)d_in[28];
    float* out = (float*)d_out;

    float *dec, *qb, *kb, *vb, *tmp2, *ff, *keys, *sc, *vs;
    __nv_bfloat16 *bthi, *btlo;
    cudaGetSymbolAddress((void**)&dec,  g_dec);
    cudaGetSymbolAddress((void**)&qb,   g_qb);
    cudaGetSymbolAddress((void**)&kb,   g_kb);
    cudaGetSymbolAddress((void**)&vb,   g_vb);
    cudaGetSymbolAddress((void**)&tmp2, g_tmp2);
    cudaGetSymbolAddress((void**)&ff,   g_ff);
    cudaGetSymbolAddress((void**)&keys, g_keys);
    cudaGetSymbolAddress((void**)&sc,   g_sc);
    cudaGetSymbolAddress((void**)&vs,   g_vs);
    cudaGetSymbolAddress((void**)&bthi, g_bthi);
    cudaGetSymbolAddress((void**)&btlo, g_btlo);

    cudaFuncSetAttribute(gemm_mma_kernel, cudaFuncAttributeMaxDynamicSharedMemorySize, GEMM_SMEM);

    cudaMemcpyAsync(dec, s_in, sizeof(float) * NTOK * DMODEL, cudaMemcpyDeviceToDevice);

    for (int l = 0; l < 2; l++) {
        const size_t wo = (size_t)l * DMODEL * DMODEL;
        // causal self-attention
        tc_gemm(dec, Wq + wo, nullptr, qb, NTOK, DMODEL, DMODEL, 0, bthi, btlo);
        tc_gemm(dec, Wk + wo, nullptr, kb, NTOK, DMODEL, DMODEL, 0, bthi, btlo);
        tc_gemm(dec, Wv + wo, nullptr, vb, NTOK, DMODEL, DMODEL, 0, bthi, btlo);
        attn_scores_kernel<<<dim3(16, 16, 64), 256>>>(qb, kb, sc);
        softmax_kernel<<<64 * SEQ, 256>>>(sc, sc, SEQ);
        attn_out_kernel<<<dim3(1, 16, 64), 256>>>(sc, vb, qb);
        tc_gemm(qb, Wo + wo, nullptr, tmp2, NTOK, DMODEL, DMODEL, 0, bthi, btlo);
        ln_kernel<<<NTOK, 128>>>(dec, tmp2, ln1_s + l * DMODEL, ln1_b + l * DMODEL, dec);
        // cross-attention (eye mask -> o = (t @ cWv) @ cWo)
        tc_gemm(t_in, cWv + wo, nullptr, qb, NTOK, DMODEL, DMODEL, 0, bthi, btlo);
        tc_gemm(qb, cWo + wo, nullptr, tmp2, NTOK, DMODEL, DMODEL, 0, bthi, btlo);
        ln_kernel<<<NTOK, 128>>>(dec, tmp2, ln2_s + l * DMODEL, ln2_b + l * DMODEL, dec);
        // FFN
        tc_gemm(dec, W1 + (size_t)l * DMODEL * FFDIM, b1 + (size_t)l * FFDIM, ff,
                NTOK, FFDIM, DMODEL, 1, bthi, btlo);
        tc_gemm(ff, W2 + (size_t)l * FFDIM * DMODEL, b2 + (size_t)l * DMODEL, tmp2,
                NTOK, DMODEL, FFDIM, 0, bthi, btlo);
        ln_kernel<<<NTOK, 128>>>(dec, tmp2, ln3_s + l * DMODEL, ln3_b + l * DMODEL, dec);
    }

    // final head
    ln_kernel<<<NTOK, 128>>>(dec, nullptr, lnf_s, lnf_b, tmp2);
    tc_gemm(tmp2, Wout, bout, qb, NTOK, DMODEL, DMODEL, 0, bthi, btlo);
    softmax_kernel<<<NTOK, 256>>>(qb, keys, DMODEL);

    float* out_v  = out;
    float* out_s  = out + 262144;
    float* out_ss = out + 262144 + 8192;

    tc_gemm(keys, W_ss, b_ss, out_ss, NTOK, NSLOTS, DMODEL, 0, bthi, btlo);
    tc_gemm(keys, W_vs, b_vs, vs, NTOK, NSLOTS * OUTD, DMODEL, 0, bthi, btlo);
    score_argmax_kernel<<<NTOK, 256>>>(vs, x_in, out_ss, out_v, out_s);
}

// round 4
// speedup vs baseline: 1.9965x; 1.0641x over previous
#include <cuda_runtime.h>
#include <cuda_bf16.h>
#include <math.h>
#include <stdint.h>

#define NTOK   8192
#define DMODEL 512
#define HEADS  8
#define HD     64
#define SEQ    1024
#define FFDIM  2048
#define NSLOTS 512
#define OUTD   32
#define NEGF   (-3.4028234663852886e38f)

// ---------------- static scratch ----------------
__device__ float g_dec [NTOK * DMODEL];
__device__ float g_qb  [NTOK * DMODEL];
__device__ float g_kb  [NTOK * DMODEL];
__device__ float g_vb  [NTOK * DMODEL];
__device__ float g_tmp2[NTOK * DMODEL];
__device__ float g_ff  [NTOK * FFDIM];
__device__ float g_keys[NTOK * DMODEL];
__device__ float g_sc  [(size_t)64 * SEQ * SEQ];
__device__ float g_vs  [(size_t)NTOK * NSLOTS * OUTD];
__device__ __nv_bfloat16 g_bthi[8388608];     // transposed weight hi [N,K]
__device__ __nv_bfloat16 g_btlo[8388608];     // transposed weight lo [N,K]
__device__ __nv_bfloat16 g_vthi[64 * HD * SEQ]; // V^T per head, hi
__device__ __nv_bfloat16 g_vtlo[64 * HD * SEQ]; // V^T per head, lo

__device__ __forceinline__ uint32_t smem_u32(const void* p) {
    uint32_t a;
    asm("{ .reg .u64 t; cvta.to.shared.u64 t, %1; cvt.u32.u64 %0, t; }" : "=r"(a) : "l"(p));
    return a;
}
__device__ __forceinline__ uint32_t pack2(__nv_bfloat16 a, __nv_bfloat16 b) {
    return (uint32_t)__bfloat16_as_ushort(a) | ((uint32_t)__bfloat16_as_ushort(b) << 16);
}
__device__ __forceinline__ void cp16(uint32_t dst, const void* src) {
    asm volatile("cp.async.cg.shared.global [%0], [%1], 16;" :: "r"(dst), "l"(src) : "memory");
}
__device__ __forceinline__ void cp_commit_waitall() {
    asm volatile("cp.async.commit_group;" ::: "memory");
    asm volatile("cp.async.wait_group 0;" ::: "memory");
}

#define LDMX4(r0, r1, r2, r3, addr) \
    asm volatile("ldmatrix.sync.aligned.m8n8.x4.shared.b16 {%0,%1,%2,%3}, [%4];" \
        : "=r"(r0), "=r"(r1), "=r"(r2), "=r"(r3) : "r"(addr))

#define MMA_BF16(c, a, b) \
    asm volatile("mma.sync.aligned.m16n8k16.row.col.f32.bf16.bf16.f32 " \
        "{%0,%1,%2,%3}, {%4,%5,%6,%7}, {%8,%9}, {%0,%1,%2,%3};" \
        : "+f"((c)[0]), "+f"((c)[1]), "+f"((c)[2]), "+f"((c)[3]) \
        : "r"((a)[0]), "r"((a)[1]), "r"((a)[2]), "r"((a)[3]), "r"((b)[0]), "r"((b)[1]))

#define LDP 72                           // padded bf16 row stride (144B, conflict-free)
#define TILE_ELEMS (128 * LDP)
#define GEMM_SMEM (4 * TILE_ELEMS * 2)   // 73728 B
#define ASC_SMEM  (4 * TILE_ELEMS * 2)   // 73728 B
#define AO_SMEM   ((2 * 128 + 2 * 64) * LDP * 2)  // 55296 B

// helper: fp32x4 -> hi/lo packed
__device__ __forceinline__ void split4(float4 v, uint2& hi, uint2& lo) {
    __nv_bfloat16 hx = __float2bfloat16(v.x), hy = __float2bfloat16(v.y);
    __nv_bfloat16 hz = __float2bfloat16(v.z), hw = __float2bfloat16(v.w);
    __nv_bfloat16 lx = __float2bfloat16(v.x - __bfloat162float(hx));
    __nv_bfloat16 ly = __float2bfloat16(v.y - __bfloat162float(hy));
    __nv_bfloat16 lz = __float2bfloat16(v.z - __bfloat162float(hz));
    __nv_bfloat16 lw = __float2bfloat16(v.w - __bfloat162float(hw));
    hi = make_uint2(pack2(hx, hy), pack2(hz, hw));
    lo = make_uint2(pack2(lx, ly), pack2(lz, lw));
}

// ============ split-bf16 HMMA GEMM, 512 threads: C = A[M,K] @ Bt[N,K]^T ========
__global__ __launch_bounds__(512, 1)
void gemm_mma_kernel(const float* __restrict__ A,
                     const __nv_bfloat16* __restrict__ Bhi,
                     const __nv_bfloat16* __restrict__ Blo,
                     const float* __restrict__ bias, float* __restrict__ C,
                     int M, int N, int K, int relu)
{
    extern __shared__ char smem[];
    __nv_bfloat16* sAh = (__nv_bfloat16*)smem;
    __nv_bfloat16* sAl = sAh + TILE_ELEMS;
    __nv_bfloat16* sBh = sAl + TILE_ELEMS;
    __nv_bfloat16* sBl = sBh + TILE_ELEMS;

    const int tid  = threadIdx.x;
    const int lane = tid & 31;
    const int wid  = tid >> 5;
    const int wm   = wid >> 2;           // 0..3 -> 32-row warp tile
    const int wn   = wid & 3;            // 0..3 -> 32-col warp tile
    const size_t brow = (size_t)blockIdx.y * 128;
    const size_t bcol = (size_t)blockIdx.x * 128;

    const int a_kg = tid & 15, a_r0 = tid >> 4;   // A: float4, 32 rows/iter
    const int b_kg = tid & 7,  b_r0 = tid >> 3;   // B: 16B cp.async, 64 rows/iter

    float4 aReg[4];
    const int NP = K >> 6;
    {
        const float* ap = A + (brow + a_r0) * K + a_kg * 4;
#pragma unroll
        for (int it = 0; it < 4; it++) aReg[it] = *(const float4*)(ap + (size_t)(it * 32) * K);
    }

    float acc[2][4][4];
#pragma unroll
    for (int i = 0; i < 2; i++)
#pragma unroll
        for (int j = 0; j < 4; j++)
#pragma unroll
            for (int c = 0; c < 4; c++) acc[i][j][c] = 0.f;

    const int lm_r = (lane & 7) + ((lane >> 3) & 1) * 8;
    const int lm_c = ((lane >> 4) & 1) * 8;
    const int lb_r = (lane & 7) + ((lane >> 4) & 1) * 8;
    const int lb_c = ((lane >> 3) & 1) * 8;

    for (int p = 0; p < NP; p++) {
        if (p > 0) __syncthreads();
        // A regs -> smem (split)
#pragma unroll
        for (int it = 0; it < 4; it++) {
            uint2 hi, lo;
            split4(aReg[it], hi, lo);
            const int off = (a_r0 + it * 32) * LDP + a_kg * 4;
            *(uint2*)(sAh + off) = hi;
            *(uint2*)(sAl + off) = lo;
        }
        // B panel via cp.async
        {
            const __nv_bfloat16* bh = Bhi + (bcol + b_r0) * K + (size_t)p * 64 + b_kg * 8;
            const __nv_bfloat16* bl = Blo + (bcol + b_r0) * K + (size_t)p * 64 + b_kg * 8;
            const int off = b_r0 * LDP + b_kg * 8;
#pragma unroll
            for (int it = 0; it < 2; it++) {
                cp16(smem_u32(sBh + off + it * 64 * LDP), bh + (size_t)(it * 64) * K);
                cp16(smem_u32(sBl + off + it * 64 * LDP), bl + (size_t)(it * 64) * K);
            }
        }
        // prefetch next A
        if (p + 1 < NP) {
            const float* ap = A + (brow + a_r0) * K + (size_t)(p + 1) * 64 + a_kg * 4;
#pragma unroll
            for (int it = 0; it < 4; it++) aReg[it] = *(const float4*)(ap + (size_t)(it * 32) * K);
        }
        cp_commit_waitall();
        __syncthreads();

#pragma unroll
        for (int ks = 0; ks < 4; ks++) {
            const int k0 = ks * 16;
            uint32_t Ah[2][4], Al[2][4], Bh[4][2], Bl[4][2];
#pragma unroll
            for (int mi = 0; mi < 2; mi++) {
                const int r = wm * 32 + mi * 16 + lm_r;
                LDMX4(Ah[mi][0], Ah[mi][1], Ah[mi][2], Ah[mi][3], smem_u32(sAh + r * LDP + k0 + lm_c));
                LDMX4(Al[mi][0], Al[mi][1], Al[mi][2], Al[mi][3], smem_u32(sAl + r * LDP + k0 + lm_c));
            }
#pragma unroll
            for (int nio = 0; nio < 2; nio++) {
                const int r = wn * 32 + nio * 16 + lb_r;
                LDMX4(Bh[2*nio][0], Bh[2*nio][1], Bh[2*nio+1][0], Bh[2*nio+1][1],
                      smem_u32(sBh + r * LDP + k0 + lb_c));
                LDMX4(Bl[2*nio][0], Bl[2*nio][1], Bl[2*nio+1][0], Bl[2*nio+1][1],
                      smem_u32(sBl + r * LDP + k0 + lb_c));
            }
#pragma unroll
            for (int mi = 0; mi < 2; mi++)
#pragma unroll
                for (int ni = 0; ni < 4; ni++) {
                    MMA_BF16(acc[mi][ni], Ah[mi], Bh[ni]);
                    MMA_BF16(acc[mi][ni], Ah[mi], Bl[ni]);
                    MMA_BF16(acc[mi][ni], Al[mi], Bh[ni]);
                }
        }
    }

    const int g = lane >> 2, t = lane & 3;
#pragma unroll
    for (int mi = 0; mi < 2; mi++) {
        const size_t rm = brow + wm * 32 + mi * 16 + g;
#pragma unroll
        for (int ni = 0; ni < 4; ni++) {
            const size_t cn = bcol + wn * 32 + ni * 8 + 2 * t;
            float b0 = 0.f, b1 = 0.f;
            if (bias) { b0 = bias[cn]; b1 = bias[cn + 1]; }
            float2 o0 = make_float2(acc[mi][ni][0] + b0, acc[mi][ni][1] + b1);
            float2 o1 = make_float2(acc[mi][ni][2] + b0, acc[mi][ni][3] + b1);
            if (relu) {
                o0.x = fmaxf(o0.x, 0.f); o0.y = fmaxf(o0.y, 0.f);
                o1.x = fmaxf(o1.x, 0.f); o1.y = fmaxf(o1.y, 0.f);
            }
            *(float2*)(C + rm * N + cn)       = o0;
            *(float2*)(C + (rm + 8) * N + cn) = o1;
        }
    }
}

// ============ attention scores via HMMA: S = (Q K^T)/8 with causal mask ========
// grid (kt 8, qt 8, bh 64), 256 threads (8 warps, 64x32 warp tiles)
__global__ __launch_bounds__(256, 1)
void attn_scores_mma(const float* __restrict__ Q, const float* __restrict__ Kg,
                     float* __restrict__ S)
{
    const int kt = blockIdx.x, qt = blockIdx.y, bh = blockIdx.z;
    const int b = bh >> 3, h = bh & 7;
    const int tid = threadIdx.x;
    const size_t sbase = (size_t)bh * SEQ * SEQ;

    if (kt > qt) {
#pragma unroll
        for (int i = 0; i < 64; i++) {
            int v = tid + i * 256;                 // 16384 elems
            int r = v >> 7, c = v & 127;
            S[sbase + (size_t)(qt * 128 + r) * SEQ + kt * 128 + c] = NEGF;
        }
        return;
    }

    extern __shared__ char smem[];
    __nv_bfloat16* sAh = (__nv_bfloat16*)smem;
    __nv_bfloat16* sAl = sAh + TILE_ELEMS;
    __nv_bfloat16* sBh = sAl + TILE_ELEMS;
    __nv_bfloat16* sBl = sBh + TILE_ELEMS;

    const int lane = tid & 31;
    const int wid  = tid >> 5;
    const int wm   = wid >> 2;            // 0..1 -> 64 rows
    const int wn   = wid & 3;             // 0..3 -> 32 cols

    // load Q,K tiles (fp32 -> hi/lo), 128 rows x 64 cols each
    const int kg = tid & 15, r0 = tid >> 4;
#pragma unroll
    for (int it = 0; it < 8; it++) {
        const int r = r0 + it * 16;
        float4 qv = *(const float4*)(Q + ((size_t)(b * SEQ + qt * 128 + r) * DMODEL) + h * HD + kg * 4);
        float4 kv = *(const float4*)(Kg + ((size_t)(b * SEQ + kt * 128 + r) * DMODEL) + h * HD + kg * 4);
        uint2 hi, lo;
        const int off = r * LDP + kg * 4;
        split4(qv, hi, lo);
        *(uint2*)(sAh + off) = hi; *(uint2*)(sAl + off) = lo;
        split4(kv, hi, lo);
        *(uint2*)(sBh + off) = hi; *(uint2*)(sBl + off) = lo;
    }
    __syncthreads();

    const int lm_r = (lane & 7) + ((lane >> 3) & 1) * 8;
    const int lm_c = ((lane >> 4) & 1) * 8;
    const int lb_r = (lane & 7) + ((lane >> 4) & 1) * 8;
    const int lb_c = ((lane >> 3) & 1) * 8;

    float acc[4][4][4];
#pragma unroll
    for (int i = 0; i < 4; i++)
#pragma unroll
        for (int j = 0; j < 4; j++)
#pragma unroll
            for (int c = 0; c < 4; c++) acc[i][j][c] = 0.f;

#pragma unroll
    for (int ks = 0; ks < 4; ks++) {
        const int k0 = ks * 16;
        uint32_t Ah[4][4], Al[4][4], Bh[4][2], Bl[4][2];
#pragma unroll
        for (int mi = 0; mi < 4; mi++) {
            const int r = wm * 64 + mi * 16 + lm_r;
            LDMX4(Ah[mi][0], Ah[mi][1], Ah[mi][2], Ah[mi][3], smem_u32(sAh + r * LDP + k0 + lm_c));
            LDMX4(Al[mi][0], Al[mi][1], Al[mi][2], Al[mi][3], smem_u32(sAl + r * LDP + k0 + lm_c));
        }
#pragma unroll
        for (int nio = 0; nio < 2; nio++) {
            const int r = wn * 32 + nio * 16 + lb_r;
            LDMX4(Bh[2*nio][0], Bh[2*nio][1], Bh[2*nio+1][0], Bh[2*nio+1][1],
                  smem_u32(sBh + r * LDP + k0 + lb_c));
            LDMX4(Bl[2*nio][0], Bl[2*nio][1], Bl[2*nio+1][0], Bl[2*nio+1][1],
                  smem_u32(sBl + r * LDP + k0 + lb_c));
        }
#pragma unroll
        for (int mi = 0; mi < 4; mi++)
#pragma unroll
            for (int ni = 0; ni < 4; ni++) {
                MMA_BF16(acc[mi][ni], Ah[mi], Bh[ni]);
                MMA_BF16(acc[mi][ni], Ah[mi], Bl[ni]);
                MMA_BF16(acc[mi][ni], Al[mi], Bh[ni]);
            }
    }

    const int g = lane >> 2, t = lane & 3;
#pragma unroll
    for (int mi = 0; mi < 4; mi++) {
        const int q = qt * 128 + wm * 64 + mi * 16 + g;
#pragma unroll
        for (int ni = 0; ni < 4; ni++) {
            const int kc = kt * 128 + wn * 32 + ni * 8 + 2 * t;
            float2 o0, o1;
            o0.x = (kc     <= q    ) ? acc[mi][ni][0] * 0.125f : NEGF;
            o0.y = (kc + 1 <= q    ) ? acc[mi][ni][1] * 0.125f : NEGF;
            o1.x = (kc     <= q + 8) ? acc[mi][ni][2] * 0.125f : NEGF;
            o1.y = (kc + 1 <= q + 8) ? acc[mi][ni][3] * 0.125f : NEGF;
            *(float2*)(S + sbase + (size_t)q * SEQ + kc)       = o0;
            *(float2*)(S + sbase + (size_t)(q + 8) * SEQ + kc) = o1;
        }
    }
}

// ============ V^T convert: vb[tok,512] -> per-head [d, k] hi/lo bf16 ==========
// grid (k/32=32, d/32=2, bh=64), block 256
__global__ void vt_convert_kernel(const float* __restrict__ V,
                                  __nv_bfloat16* __restrict__ Hi,
                                  __nv_bfloat16* __restrict__ Lo)
{
    __shared__ float t[32][33];
    const int k0 = blockIdx.x * 32, d0 = blockIdx.y * 32, bh = blockIdx.z;
    const int b = bh >> 3, h = bh & 7;
    const int tx = threadIdx.x & 31, ty = threadIdx.x >> 5;
#pragma unroll
    for (int j = 0; j < 32; j += 8)
        t[ty + j][tx] = V[((size_t)(b * SEQ + k0 + ty + j) * DMODEL) + h * HD + d0 + tx];
    __syncthreads();
#pragma unroll
    for (int j = 0; j < 32; j += 8) {
        float v = t[tx][ty + j];
        __nv_bfloat16 hi = __float2bfloat16(v);
        __nv_bfloat16 lo = __float2bfloat16(v - __bfloat162float(hi));
        const size_t o = ((size_t)bh * HD + d0 + ty + j) * SEQ + k0 + tx;
        Hi[o] = hi;
        Lo[o] = lo;
    }
}

// ============ attention output via HMMA: O = P @ V ===========================
// grid (qt 8, bh 64), 256 threads (8 warps, 32x32 warp tiles over 128x64)
__global__ __launch_bounds__(256, 1)
void attn_out_mma(const float* __restrict__ P, const __nv_bfloat16* __restrict__ Vthi,
                  const __nv_bfloat16* __restrict__ Vtlo, float* __restrict__ O)
{
    const int qt = blockIdx.x, bh = blockIdx.y;
    const int b = bh >> 3, h = bh & 7;
    const int tid = threadIdx.x;
    const size_t pbase = (size_t)bh * SEQ * SEQ;

    extern __shared__ char smem[];
    __nv_bfloat16* sPh = (__nv_bfloat16*)smem;
    __nv_bfloat16* sPl = sPh + TILE_ELEMS;
    __nv_bfloat16* sVh = sPl + TILE_ELEMS;
    __nv_bfloat16* sVl = sVh + 64 * LDP;

    const int lane = tid & 31;
    const int wid  = tid >> 5;
    const int wm   = wid >> 1;            // 0..3 -> 32 rows
    const int wn   = wid & 1;             // 0..1 -> 32 cols

    const int p_kg = tid & 15, p_r0 = tid >> 4;   // P loads: 16 rows/iter, 8 iters
    const int v_kg = tid & 7,  v_r0 = tid >> 3;   // V loads: 32 rows/iter, 2 iters

    const int nch = (qt + 1) * 2;

    float4 pReg[8];
    uint4  vhReg[2], vlReg[2];
    {
        const float* pp = P + pbase + (size_t)(qt * 128 + p_r0) * SEQ + p_kg * 4;
#pragma unroll
        for (int it = 0; it < 8; it++) pReg[it] = *(const float4*)(pp + (size_t)(it * 16) * SEQ);
        const __nv_bfloat16* vh = Vthi + ((size_t)bh * HD + v_r0) * SEQ + v_kg * 8;
        const __nv_bfloat16* vl = Vtlo + ((size_t)bh * HD + v_r0) * SEQ + v_kg * 8;
#pragma unroll
        for (int it = 0; it < 2; it++) {
            vhReg[it] = *(const uint4*)(vh + (size_t)(it * 32) * SEQ);
            vlReg[it] = *(const uint4*)(vl + (size_t)(it * 32) * SEQ);
        }
    }

    float acc[2][4][4];
#pragma unroll
    for (int i = 0; i < 2; i++)
#pragma unroll
        for (int j = 0; j < 4; j++)
#pragma unroll
            for (int c = 0; c < 4; c++) acc[i][j][c] = 0.f;

    const int lm_r = (lane & 7) + ((lane >> 3) & 1) * 8;
    const int lm_c = ((lane >> 4) & 1) * 8;
    const int lb_r = (lane & 7) + ((lane >> 4) & 1) * 8;
    const int lb_c = ((lane >> 3) & 1) * 8;

    for (int kc = 0; kc < nch; kc++) {
        if (kc > 0) __syncthreads();
#pragma unroll
        for (int it = 0; it < 8; it++) {
            uint2 hi, lo;
            split4(pReg[it], hi, lo);
            const int off = (p_r0 + it * 16) * LDP + p_kg * 4;
            *(uint2*)(sPh + off) = hi;
            *(uint2*)(sPl + off) = lo;
        }
#pragma unroll
        for (int it = 0; it < 2; it++) {
            const int off = (v_r0 + it * 32) * LDP + v_kg * 8;
            *(uint4*)(sVh + off) = vhReg[it];
            *(uint4*)(sVl + off) = vlReg[it];
        }
        __syncthreads();

        if (kc + 1 < nch) {
            const float* pp = P + pbase + (size_t)(qt * 128 + p_r0) * SEQ + (kc + 1) * 64 + p_kg * 4;
#pragma unroll
            for (int it = 0; it < 8; it++) pReg[it] = *(const float4*)(pp + (size_t)(it * 16) * SEQ);
            const __nv_bfloat16* vh = Vthi + ((size_t)bh * HD + v_r0) * SEQ + (kc + 1) * 64 + v_kg * 8;
            const __nv_bfloat16* vl = Vtlo + ((size_t)bh * HD + v_r0) * SEQ + (kc + 1) * 64 + v_kg * 8;
#pragma unroll
            for (int it = 0; it < 2; it++) {
                vhReg[it] = *(const uint4*)(vh + (size_t)(it * 32) * SEQ);
                vlReg[it] = *(const uint4*)(vl + (size_t)(it * 32) * SEQ);
            }
        }

#pragma unroll
        for (int ks = 0; ks < 4; ks++) {
            const int k0 = ks * 16;
            uint32_t Ah[2][4], Al[2][4], Bh[4][2], Bl[4][2];
#pragma unroll
            for (int mi = 0; mi < 2; mi++) {
                const int r = wm * 32 + mi * 16 + lm_r;
                LDMX4(Ah[mi][0], Ah[mi][1], Ah[mi][2], Ah[mi][3], smem_u32(sPh + r * LDP + k0 + lm_c));
                LDMX4(Al[mi][0], Al[mi][1], Al[mi][2], Al[mi][3], smem_u32(sPl + r * LDP + k0 + lm_c));
            }
#pragma unroll
            for (int nio = 0; nio < 2; nio++) {
                const int r = wn * 32 + nio * 16 + lb_r;
                LDMX4(Bh[2*nio][0], Bh[2*nio][1], Bh[2*nio+1][0], Bh[2*nio+1][1],
                      smem_u32(sVh + r * LDP + k0 + lb_c));
                LDMX4(Bl[2*nio][0], Bl[2*nio][1], Bl[2*nio+1][0], Bl[2*nio+1][1],
                      smem_u32(sVl + r * LDP + k0 + lb_c));
            }
#pragma unroll
            for (int mi = 0; mi < 2; mi++)
#pragma unroll
                for (int ni = 0; ni < 4; ni++) {
                    MMA_BF16(acc[mi][ni], Ah[mi], Bh[ni]);
                    MMA_BF16(acc[mi][ni], Ah[mi], Bl[ni]);
                    MMA_BF16(acc[mi][ni], Al[mi], Bh[ni]);
                }
        }
    }

    const int g = lane >> 2, t = lane & 3;
#pragma unroll
    for (int mi = 0; mi < 2; mi++) {
        const int q = qt * 128 + wm * 32 + mi * 16 + g;
#pragma unroll
        for (int ni = 0; ni < 4; ni++) {
            const int d = wn * 32 + ni * 8 + 2 * t;
            *(float2*)(O + ((size_t)(b * SEQ + q) * DMODEL) + h * HD + d) =
                make_float2(acc[mi][ni][0], acc[mi][ni][1]);
            *(float2*)(O + ((size_t)(b * SEQ + q + 8) * DMODEL) + h * HD + d) =
                make_float2(acc[mi][ni][2], acc[mi][ni][3]);
        }
    }
}

// ============ transpose + split-convert: W[K,N] fp32 -> hi/lo [N,K] bf16 ======
__global__ void transpose_convert_kernel(const float* __restrict__ W,
                                         __nv_bfloat16* __restrict__ Hi,
                                         __nv_bfloat16* __restrict__ Lo, int K, int N)
{
    __shared__ float t[32][33];
    const int k0 = blockIdx.y * 32, n0 = blockIdx.x * 32;
    const int tx = threadIdx.x & 31, ty = threadIdx.x >> 5;
#pragma unroll
    for (int j = 0; j < 32; j += 8)
        t[ty + j][tx] = W[(size_t)(k0 + ty + j) * N + n0 + tx];
    __syncthreads();
#pragma unroll
    for (int j = 0; j < 32; j += 8) {
        float v = t[tx][ty + j];
        __nv_bfloat16 h = __float2bfloat16(v);
        __nv_bfloat16 l = __float2bfloat16(v - __bfloat162float(h));
        Hi[(size_t)(n0 + ty + j) * K + k0 + tx] = h;
        Lo[(size_t)(n0 + ty + j) * K + k0 + tx] = l;
    }
}

// ---------------- row softmax ----------------
__global__ void softmax_kernel(const float* __restrict__ src, float* __restrict__ dst, int ncols)
{
    const int row = blockIdx.x;
    const int tid = threadIdx.x;
    const int warp = tid >> 5, lane = tid & 31;
    const float* p = src + (size_t)row * ncols;
    const int c = ncols >> 8;
    float v[4];
    float m = -INFINITY;
    for (int i = 0; i < c; i++) { v[i] = p[tid + i * 256]; m = fmaxf(m, v[i]); }
#pragma unroll
    for (int o = 16; o > 0; o >>= 1) m = fmaxf(m, __shfl_xor_sync(~0u, m, o));
    __shared__ float smax[8], ssum[8];
    if (lane == 0) smax[warp] = m;
    __syncthreads();
    m = smax[0];
#pragma unroll
    for (int w = 1; w < 8; w++) m = fmaxf(m, smax[w]);
    float sum = 0.f;
    for (int i = 0; i < c; i++) { v[i] = expf(v[i] - m); sum += v[i]; }
#pragma unroll
    for (int o = 16; o > 0; o >>= 1) sum += __shfl_xor_sync(~0u, sum, o);
    if (lane == 0) ssum[warp] = sum;
    __syncthreads();
    sum = ssum[0];
#pragma unroll
    for (int w = 1; w < 8; w++) sum += ssum[w];
    float inv = 1.f / sum;
    float* q = dst + (size_t)row * ncols;
    for (int i = 0; i < c; i++) q[tid + i * 256] = v[i] * inv;
}

// ---------------- residual + LayerNorm ----------------
__global__ void ln_kernel(const float* __restrict__ xin, const float* __restrict__ res,
                          const float* __restrict__ scale, const float* __restrict__ bias,
                          float* __restrict__ out)
{
    const int row = blockIdx.x;
    const int tid = threadIdx.x;
    float4 v = ((const float4*)(xin + (size_t)row * DMODEL))[tid];
    if (res) {
        float4 r = ((const float4*)(res + (size_t)row * DMODEL))[tid];
        v.x += r.x; v.y += r.y; v.z += r.z; v.w += r.w;
    }
    float s  = v.x + v.y + v.z + v.w;
    float sq = v.x * v.x + v.y * v.y + v.z * v.z + v.w * v.w;
#pragma unroll
    for (int o = 16; o > 0; o >>= 1) {
        s  += __shfl_xor_sync(~0u, s,  o);
        sq += __shfl_xor_sync(~0u, sq, o);
    }
    __shared__ float ss[4], sqs[4];
    const int warp = tid >> 5, lane = tid & 31;
    if (lane == 0) { ss[warp] = s; sqs[warp] = sq; }
    __syncthreads();
    float S  = ss[0]  + ss[1]  + ss[2]  + ss[3];
    float SQ = sqs[0] + sqs[1] + sqs[2] + sqs[3];
    float mean = S * (1.f / DMODEL);
    float var  = SQ * (1.f / DMODEL) - mean * mean;
    float rs   = rsqrtf(var + 1e-6f);
    float4 sc4 = ((const float4*)scale)[tid];
    float4 bi4 = ((const float4*)bias)[tid];
    float4 o;
    o.x = (v.x - mean) * rs * sc4.x + bi4.x;
    o.y = (v.y - mean) * rs * sc4.y + bi4.y;
    o.z = (v.z - mean) * rs * sc4.z + bi4.z;
    o.w = (v.w - mean) * rs * sc4.w + bi4.w;
    ((float4*)(out + (size_t)row * DMODEL))[tid] = o;
}

// ---------------- cosine-score argmax + gather ----------------
__global__ void score_argmax_kernel(const float* __restrict__ Vs, const float* __restrict__ x,
                                    const float* __restrict__ Ss, float* __restrict__ vout,
                                    float* __restrict__ sout)
{
    const int n = blockIdx.x;
    const int tid = threadIdx.x;
    const int warp = tid >> 5, lane = tid & 31;
    __shared__ float xs[32];
    __shared__ float wbest[8];
    __shared__ int   widx[8];
    if (tid < 32) xs[tid] = x[(size_t)n * OUTD + tid];
    __syncthreads();
    const float xv = xs[lane];
    const float* vrow = Vs + (size_t)n * NSLOTS * OUTD;

    float best = -INFINITY;
    int   bidx = 0;
    for (int k = warp; k < NSLOTS; k += 8) {
        float v = vrow[k * OUTD + lane];
        float d = v * xv;
        float s = v * v;
#pragma unroll
        for (int o = 16; o > 0; o >>= 1) {
            d += __shfl_xor_sync(~0u, d, o);
            s += __shfl_xor_sync(~0u, s, o);
        }
        float sc = d / sqrtf(s);
        if (sc > best) { best = sc; bidx = k; }
    }
    if (lane == 0) { wbest[warp] = best; widx[warp] = bidx; }
    __syncthreads();
    if (tid == 0) {
        float b = wbest[0]; int bi = widx[0];
        for (int w = 1; w < 8; w++)
            if (wbest[w] > b || (wbest[w] == b && widx[w] < bi)) { b = wbest[w]; bi = widx[w]; }
        widx[0] = bi;
    }
    __syncthreads();
    const int idx = widx[0];
    if (tid < 32) vout[(size_t)n * OUTD + tid] = vrow[idx * OUTD + tid];
    if (tid == 0) sout[n] = Ss[(size_t)n * NSLOTS + idx];
}

// ---------------- host-side GEMM wrapper ----------------
static void tc_gemm(const float* A, const float* W, const float* bias, float* C,
                    int M, int N, int K, int relu,
                    __nv_bfloat16* bthi, __nv_bfloat16* btlo)
{
    transpose_convert_kernel<<<dim3(N / 32, K / 32), 256>>>(W, bthi, btlo, K, N);
    gemm_mma_kernel<<<dim3(N / 128, M / 128), 512, GEMM_SMEM>>>(A, bthi, btlo, bias, C, M, N, K, relu);
}

// ---------------- launch ----------------
extern "C" void kernel_launch(void* const* d_in, const int* in_sizes, int n_in,
                              void* d_out, int out_size)
{
    const float* s_in  = (const float*)d_in[0];
    const float* x_in  = (const float*)d_in[1];
    const float* t_in  = (const float*)d_in[2];
    const float* Wq    = (const float*)d_in[3];
    const float* Wk    = (const float*)d_in[4];
    const float* Wv    = (const float*)d_in[5];
    const float* Wo    = (const float*)d_in[6];
    const float* cWv   = (const float*)d_in[9];
    const float* cWo   = (const float*)d_in[10];
    const float* ln1_s = (const float*)d_in[11];
    const float* ln1_b = (const float*)d_in[12];
    const float* ln2_s = (const float*)d_in[13];
    const float* ln2_b = (const float*)d_in[14];
    const float* ln3_s = (const float*)d_in[15];
    const float* ln3_b = (const float*)d_in[16];
    const float* W1    = (const float*)d_in[17];
    const float* b1    = (const float*)d_in[18];
    const float* W2    = (const float*)d_in[19];
    const float* b2    = (const float*)d_in[20];
    const float* lnf_s = (const float*)d_in[21];
    const float* lnf_b = (const float*)d_in[22];
    const float* Wout  = (const float*)d_in[23];
    const float* bout  = (const float*)d_in[24];
    const float* W_vs  = (const float*)d_in[25];
    const float* b_vs  = (const float*)d_in[26];
    const float* W_ss  = (const float*)d_in[27];
    const float* b_ss  = (const float*)d_in[28];
    float* out = (float*)d_out;

    float *dec, *qb, *kb, *vb, *tmp2, *ff, *keys, *sc, *vs;
    __nv_bfloat16 *bthi, *btlo, *vthi, *vtlo;
    cudaGetSymbolAddress((void**)&dec,  g_dec);
    cudaGetSymbolAddress((void**)&qb,   g_qb);
    cudaGetSymbolAddress((void**)&kb,   g_kb);
    cudaGetSymbolAddress((void**)&vb,   g_vb);
    cudaGetSymbolAddress((void**)&tmp2, g_tmp2);
    cudaGetSymbolAddress((void**)&ff,   g_ff);
    cudaGetSymbolAddress((void**)&keys, g_keys);
    cudaGetSymbolAddress((void**)&sc,   g_sc);
    cudaGetSymbolAddress((void**)&vs,   g_vs);
    cudaGetSymbolAddress((void**)&bthi, g_bthi);
    cudaGetSymbolAddress((void**)&btlo, g_btlo);
    cudaGetSymbolAddress((void**)&vthi, g_vthi);
    cudaGetSymbolAddress((void**)&vtlo, g_vtlo);

    cudaFuncSetAttribute(gemm_mma_kernel, cudaFuncAttributeMaxDynamicSharedMemorySize, GEMM_SMEM);
    cudaFuncSetAttribute(attn_scores_mma, cudaFuncAttributeMaxDynamicSharedMemorySize, ASC_SMEM);
    cudaFuncSetAttribute(attn_out_mma,    cudaFuncAttributeMaxDynamicSharedMemorySize, AO_SMEM);

    cudaMemcpyAsync(dec, s_in, sizeof(float) * NTOK * DMODEL, cudaMemcpyDeviceToDevice);

    for (int l = 0; l < 2; l++) {
        const size_t wo = (size_t)l * DMODEL * DMODEL;
        // causal self-attention
        tc_gemm(dec, Wq + wo, nullptr, qb, NTOK, DMODEL, DMODEL, 0, bthi, btlo);
        tc_gemm(dec, Wk + wo, nullptr, kb, NTOK, DMODEL, DMODEL, 0, bthi, btlo);
        tc_gemm(dec, Wv + wo, nullptr, vb, NTOK, DMODEL, DMODEL, 0, bthi, btlo);
        attn_scores_mma<<<dim3(8, 8, 64), 256, ASC_SMEM>>>(qb, kb, sc);
        softmax_kernel<<<64 * SEQ, 256>>>(sc, sc, SEQ);
        vt_convert_kernel<<<dim3(32, 2, 64), 256>>>(vb, vthi, vtlo);
        attn_out_mma<<<dim3(8, 64), 256, AO_SMEM>>>(sc, vthi, vtlo, qb);
        tc_gemm(qb, Wo + wo, nullptr, tmp2, NTOK, DMODEL, DMODEL, 0, bthi, btlo);
        ln_kernel<<<NTOK, 128>>>(dec, tmp2, ln1_s + l * DMODEL, ln1_b + l * DMODEL, dec);
        // cross-attention (eye mask -> o = (t @ cWv) @ cWo)
        tc_gemm(t_in, cWv + wo, nullptr, qb, NTOK, DMODEL, DMODEL, 0, bthi, btlo);
        tc_gemm(qb, cWo + wo, nullptr, tmp2, NTOK, DMODEL, DMODEL, 0, bthi, btlo);
        ln_kernel<<<NTOK, 128>>>(dec, tmp2, ln2_s + l * DMODEL, ln2_b + l * DMODEL, dec);
        // FFN
        tc_gemm(dec, W1 + (size_t)l * DMODEL * FFDIM, b1 + (size_t)l * FFDIM, ff,
                NTOK, FFDIM, DMODEL, 1, bthi, btlo);
        tc_gemm(ff, W2 + (size_t)l * FFDIM * DMODEL, b2 + (size_t)l * DMODEL, tmp2,
                NTOK, DMODEL, FFDIM, 0, bthi, btlo);
        ln_kernel<<<NTOK, 128>>>(dec, tmp2, ln3_s + l * DMODEL, ln3_b + l * DMODEL, dec);
    }

    // final head
    ln_kernel<<<NTOK, 128>>>(dec, nullptr, lnf_s, lnf_b, tmp2);
    tc_gemm(tmp2, Wout, bout, qb, NTOK, DMODEL, DMODEL, 0, bthi, btlo);
    softmax_kernel<<<NTOK, 256>>>(qb, keys, DMODEL);

    float* out_v  = out;
    float* out_s  = out + 262144;
    float* out_ss = out + 262144 + 8192;

    tc_gemm(keys, W_ss, b_ss, out_ss, NTOK, NSLOTS, DMODEL, 0, bthi, btlo);
    tc_gemm(keys, W_vs, b_vs, vs, NTOK, NSLOTS * OUTD, DMODEL, 0, bthi, btlo);
    score_argmax_kernel<<<NTOK, 256>>>(vs, x_in, out_ss, out_v, out_s);
}

// round 5
// speedup vs baseline: 2.1297x; 1.0667x over previous
#include <cuda_runtime.h>
#include <cuda_bf16.h>
#include <math.h>
#include <stdint.h>

#define NTOK   8192
#define DMODEL 512
#define HEADS  8
#define HD     64
#define SEQ    1024
#define FFDIM  2048
#define NSLOTS 512
#define OUTD   32
#define NEGF   (-3.4028234663852886e38f)

// ---------------- static scratch ----------------
__device__ float g_dec [NTOK * DMODEL];
__device__ float g_vb  [NTOK * DMODEL];
__device__ float g_tmp2[NTOK * DMODEL];
__device__ float g_sc  [(size_t)64 * SEQ * SEQ];        // fp32 scores
__device__ float g_vs  [(size_t)NTOK * NSLOTS * OUTD];  // Vs
__device__ __nv_bfloat16 g_dech[NTOK * DMODEL], g_decl[NTOK * DMODEL];
__device__ __nv_bfloat16 g_qbh [NTOK * DMODEL], g_qbl [NTOK * DMODEL];
__device__ __nv_bfloat16 g_kbh [NTOK * DMODEL], g_kbl [NTOK * DMODEL];
__device__ __nv_bfloat16 g_obh [NTOK * DMODEL], g_obl [NTOK * DMODEL];
__device__ __nv_bfloat16 g_th  [NTOK * DMODEL], g_tl  [NTOK * DMODEL];
__device__ __nv_bfloat16 g_ffh [NTOK * FFDIM],  g_ffl [NTOK * FFDIM];
__device__ __nv_bfloat16 g_keysh[NTOK * DMODEL], g_keysl[NTOK * DMODEL];
__device__ __nv_bfloat16 g_ph[(size_t)64 * SEQ * SEQ], g_pl[(size_t)64 * SEQ * SEQ];
__device__ __nv_bfloat16 g_vthi[64 * HD * SEQ], g_vtlo[64 * HD * SEQ];
__device__ __nv_bfloat16 g_bthi[8388608], g_btlo[8388608];

__device__ __forceinline__ uint32_t smem_u32(const void* p) {
    uint32_t a;
    asm("{ .reg .u64 t; cvta.to.shared.u64 t, %1; cvt.u32.u64 %0, t; }" : "=r"(a) : "l"(p));
    return a;
}
__device__ __forceinline__ uint32_t pack2(__nv_bfloat16 a, __nv_bfloat16 b) {
    return (uint32_t)__bfloat16_as_ushort(a) | ((uint32_t)__bfloat16_as_ushort(b) << 16);
}
__device__ __forceinline__ void cp16(uint32_t dst, const void* src) {
    asm volatile("cp.async.cg.shared.global [%0], [%1], 16;" :: "r"(dst), "l"(src) : "memory");
}
__device__ __forceinline__ void cp_commit() {
    asm volatile("cp.async.commit_group;" ::: "memory");
}
__device__ __forceinline__ void cp_wait0() {
    asm volatile("cp.async.wait_group 0;" ::: "memory");
}
__device__ __forceinline__ void split4(float4 v, uint2& hi, uint2& lo) {
    __nv_bfloat16 hx = __float2bfloat16(v.x), hy = __float2bfloat16(v.y);
    __nv_bfloat16 hz = __float2bfloat16(v.z), hw = __float2bfloat16(v.w);
    __nv_bfloat16 lx = __float2bfloat16(v.x - __bfloat162float(hx));
    __nv_bfloat16 ly = __float2bfloat16(v.y - __bfloat162float(hy));
    __nv_bfloat16 lz = __float2bfloat16(v.z - __bfloat162float(hz));
    __nv_bfloat16 lw = __float2bfloat16(v.w - __bfloat162float(hw));
    hi = make_uint2(pack2(hx, hy), pack2(hz, hw));
    lo = make_uint2(pack2(lx, ly), pack2(lz, lw));
}

#define LDMX4(r0, r1, r2, r3, addr) \
    asm volatile("ldmatrix.sync.aligned.m8n8.x4.shared.b16 {%0,%1,%2,%3}, [%4];" \
        : "=r"(r0), "=r"(r1), "=r"(r2), "=r"(r3) : "r"(addr))

#define MMA_BF16(c, a, b) \
    asm volatile("mma.sync.aligned.m16n8k16.row.col.f32.bf16.bf16.f32 " \
        "{%0,%1,%2,%3}, {%4,%5,%6,%7}, {%8,%9}, {%0,%1,%2,%3};" \
        : "+f"((c)[0]), "+f"((c)[1]), "+f"((c)[2]), "+f"((c)[3]) \
        : "r"((a)[0]), "r"((a)[1]), "r"((a)[2]), "r"((a)[3]), "r"((b)[0]), "r"((b)[1]))

#define LDP 72                        // 144B row stride (conflict-free for ldmatrix)
#define T128 (128 * LDP * 2)          // 18432 B per 128x64 tile
#define T64  (64 * LDP * 2)           // 9216 B per 64x64 tile
#define GEMM_STAGE (4 * T128)         // 73728 B
#define GEMM_SMEM  (2 * GEMM_STAGE)   // 147456 B
#define ASC_SMEM   (4 * T128)         // 73728 B (single stage)
#define AO_STAGE   (2 * T128 + 2 * T64)  // 55296 B
#define AO_SMEM    (2 * AO_STAGE)     // 110592 B

// ============ split-bf16 HMMA GEMM: C = A[M,K] @ Bt[N,K]^T, pre-split inputs ====
// 2-stage cp.async pipeline, 512 threads, one __syncthreads per panel.
__global__ __launch_bounds__(512, 1)
void gemm_bb_kernel(const __nv_bfloat16* __restrict__ Ahi, const __nv_bfloat16* __restrict__ Alo,
                    const __nv_bfloat16* __restrict__ Bhi, const __nv_bfloat16* __restrict__ Blo,
                    const float* __restrict__ bias,
                    float* __restrict__ Cf, __nv_bfloat16* __restrict__ Chi,
                    __nv_bfloat16* __restrict__ Clo,
                    int M, int N, int K, int relu)
{
    extern __shared__ char smem[];
    const int tid  = threadIdx.x;
    const int lane = tid & 31, wid = tid >> 5;
    const int wm = wid >> 2, wn = wid & 3;
    const size_t brow = (size_t)blockIdx.y * 128;
    const size_t bcol = (size_t)blockIdx.x * 128;
    const int seg = tid & 7, r0 = tid >> 3;        // r0: 0..63

    const int NP = K >> 6;

    auto load_panel = [&](int p, int s) {
        char* base = smem + s * GEMM_STAGE;
        const size_t ka = (size_t)p * 64 + seg * 8;
#pragma unroll
        for (int hf = 0; hf < 2; hf++) {
            const int r = r0 + hf * 64;
            const uint32_t dst = smem_u32(base + (r * LDP + seg * 8) * 2);
            cp16(dst,            Ahi + (brow + r) * K + ka);
            cp16(dst + T128,     Alo + (brow + r) * K + ka);
            cp16(dst + 2 * T128, Bhi + (bcol + r) * K + ka);
            cp16(dst + 3 * T128, Blo + (bcol + r) * K + ka);
        }
        cp_commit();
    };

    load_panel(0, 0);

    float acc[2][4][4];
#pragma unroll
    for (int i = 0; i < 2; i++)
#pragma unroll
        for (int j = 0; j < 4; j++)
#pragma unroll
            for (int c = 0; c < 4; c++) acc[i][j][c] = 0.f;

    const int lm_r = (lane & 7) + ((lane >> 3) & 1) * 8;
    const int lm_c = ((lane >> 4) & 1) * 8;
    const int lb_r = (lane & 7) + ((lane >> 4) & 1) * 8;
    const int lb_c = ((lane >> 3) & 1) * 8;

    for (int p = 0; p < NP; p++) {
        const int s = p & 1;
        cp_wait0();                    // panel p resident
        __syncthreads();               // also: all threads done computing buffer s
        if (p + 1 < NP) load_panel(p + 1, s ^ 1);   // overlaps with compute below

        const __nv_bfloat16* sAh = (const __nv_bfloat16*)(smem + s * GEMM_STAGE);
        const __nv_bfloat16* sAl = (const __nv_bfloat16*)((char*)sAh + T128);
        const __nv_bfloat16* sBh = (const __nv_bfloat16*)((char*)sAh + 2 * T128);
        const __nv_bfloat16* sBl = (const __nv_bfloat16*)((char*)sAh + 3 * T128);

#pragma unroll
        for (int ks = 0; ks < 4; ks++) {
            const int k0 = ks * 16;
            uint32_t Ah[2][4], Al[2][4], Bh[4][2], Bl[4][2];
#pragma unroll
            for (int mi = 0; mi < 2; mi++) {
                const int r = wm * 32 + mi * 16 + lm_r;
                LDMX4(Ah[mi][0], Ah[mi][1], Ah[mi][2], Ah[mi][3], smem_u32(sAh + r * LDP + k0 + lm_c));
                LDMX4(Al[mi][0], Al[mi][1], Al[mi][2], Al[mi][3], smem_u32(sAl + r * LDP + k0 + lm_c));
            }
#pragma unroll
            for (int nio = 0; nio < 2; nio++) {
                const int r = wn * 32 + nio * 16 + lb_r;
                LDMX4(Bh[2*nio][0], Bh[2*nio][1], Bh[2*nio+1][0], Bh[2*nio+1][1],
                      smem_u32(sBh + r * LDP + k0 + lb_c));
                LDMX4(Bl[2*nio][0], Bl[2*nio][1], Bl[2*nio+1][0], Bl[2*nio+1][1],
                      smem_u32(sBl + r * LDP + k0 + lb_c));
            }
#pragma unroll
            for (int mi = 0; mi < 2; mi++)
#pragma unroll
                for (int ni = 0; ni < 4; ni++) {
                    MMA_BF16(acc[mi][ni], Ah[mi], Bh[ni]);
                    MMA_BF16(acc[mi][ni], Ah[mi], Bl[ni]);
                    MMA_BF16(acc[mi][ni], Al[mi], Bh[ni]);
                }
        }
    }

    // epilogue: bias/relu, optional fp32 C, optional hi/lo C
    const int g = lane >> 2, t = lane & 3;
#pragma unroll
    for (int mi = 0; mi < 2; mi++) {
        const size_t rm = brow + wm * 32 + mi * 16 + g;
#pragma unroll
        for (int ni = 0; ni < 4; ni++) {
            const size_t cn = bcol + wn * 32 + ni * 8 + 2 * t;
            float b0 = 0.f, b1 = 0.f;
            if (bias) { b0 = bias[cn]; b1 = bias[cn + 1]; }
            float v00 = acc[mi][ni][0] + b0, v01 = acc[mi][ni][1] + b1;
            float v10 = acc[mi][ni][2] + b0, v11 = acc[mi][ni][3] + b1;
            if (relu) {
                v00 = fmaxf(v00, 0.f); v01 = fmaxf(v01, 0.f);
                v10 = fmaxf(v10, 0.f); v11 = fmaxf(v11, 0.f);
            }
            if (Cf) {
                *(float2*)(Cf + rm * N + cn)       = make_float2(v00, v01);
                *(float2*)(Cf + (rm + 8) * N + cn) = make_float2(v10, v11);
            }
            if (Chi) {
                __nv_bfloat16 h00 = __float2bfloat16(v00), h01 = __float2bfloat16(v01);
                __nv_bfloat16 h10 = __float2bfloat16(v10), h11 = __float2bfloat16(v11);
                *(uint32_t*)(Chi + rm * N + cn)       = pack2(h00, h01);
                *(uint32_t*)(Chi + (rm + 8) * N + cn) = pack2(h10, h11);
                *(uint32_t*)(Clo + rm * N + cn)       =
                    pack2(__float2bfloat16(v00 - __bfloat162float(h00)),
                          __float2bfloat16(v01 - __bfloat162float(h01)));
                *(uint32_t*)(Clo + (rm + 8) * N + cn) =
                    pack2(__float2bfloat16(v10 - __bfloat162float(h10)),
                          __float2bfloat16(v11 - __bfloat162float(h11)));
            }
        }
    }
}

// ============ attention scores: S = (Q K^T)/8 (causal tiles only) =============
__global__ __launch_bounds__(256, 1)
void attn_scores_mma(const __nv_bfloat16* __restrict__ Qh, const __nv_bfloat16* __restrict__ Ql,
                     const __nv_bfloat16* __restrict__ Kh, const __nv_bfloat16* __restrict__ Kl,
                     float* __restrict__ S)
{
    const int kt = blockIdx.x, qt = blockIdx.y, bh = blockIdx.z;
    if (kt > qt) return;                          // upper tiles never read
    const int b = bh >> 3, h = bh & 7;
    const int tid = threadIdx.x;
    const size_t sbase = (size_t)bh * SEQ * SEQ;

    extern __shared__ char smem[];
    const int seg = tid & 7, r0 = tid >> 3;       // r0: 0..31
#pragma unroll
    for (int it = 0; it < 4; it++) {
        const int r = r0 + it * 32;
        const uint32_t dst = smem_u32(smem + (r * LDP + seg * 8) * 2);
        const size_t qoff = ((size_t)(b * SEQ + qt * 128 + r) * DMODEL) + h * HD + seg * 8;
        const size_t koff = ((size_t)(b * SEQ + kt * 128 + r) * DMODEL) + h * HD + seg * 8;
        cp16(dst,            Qh + qoff);
        cp16(dst + T128,     Ql + qoff);
        cp16(dst + 2 * T128, Kh + koff);
        cp16(dst + 3 * T128, Kl + koff);
    }
    cp_commit();
    cp_wait0();
    __syncthreads();

    const __nv_bfloat16* sAh = (const __nv_bfloat16*)smem;
    const __nv_bfloat16* sAl = (const __nv_bfloat16*)(smem + T128);
    const __nv_bfloat16* sBh = (const __nv_bfloat16*)(smem + 2 * T128);
    const __nv_bfloat16* sBl = (const __nv_bfloat16*)(smem + 3 * T128);

    const int lane = tid & 31, wid = tid >> 5;
    const int wm = wid >> 2, wn = wid & 3;
    const int lm_r = (lane & 7) + ((lane >> 3) & 1) * 8;
    const int lm_c = ((lane >> 4) & 1) * 8;
    const int lb_r = (lane & 7) + ((lane >> 4) & 1) * 8;
    const int lb_c = ((lane >> 3) & 1) * 8;

    float acc[4][4][4];
#pragma unroll
    for (int i = 0; i < 4; i++)
#pragma unroll
        for (int j = 0; j < 4; j++)
#pragma unroll
            for (int c = 0; c < 4; c++) acc[i][j][c] = 0.f;

#pragma unroll
    for (int ks = 0; ks < 4; ks++) {
        const int k0 = ks * 16;
        uint32_t Ah[4][4], Al[4][4], Bh[4][2], Bl[4][2];
#pragma unroll
        for (int mi = 0; mi < 4; mi++) {
            const int r = wm * 64 + mi * 16 + lm_r;
            LDMX4(Ah[mi][0], Ah[mi][1], Ah[mi][2], Ah[mi][3], smem_u32(sAh + r * LDP + k0 + lm_c));
            LDMX4(Al[mi][0], Al[mi][1], Al[mi][2], Al[mi][3], smem_u32(sAl + r * LDP + k0 + lm_c));
        }
#pragma unroll
        for (int nio = 0; nio < 2; nio++) {
            const int r = wn * 32 + nio * 16 + lb_r;
            LDMX4(Bh[2*nio][0], Bh[2*nio][1], Bh[2*nio+1][0], Bh[2*nio+1][1],
                  smem_u32(sBh + r * LDP + k0 + lb_c));
            LDMX4(Bl[2*nio][0], Bl[2*nio][1], Bl[2*nio+1][0], Bl[2*nio+1][1],
                  smem_u32(sBl + r * LDP + k0 + lb_c));
        }
#pragma unroll
        for (int mi = 0; mi < 4; mi++)
#pragma unroll
            for (int ni = 0; ni < 4; ni++) {
                MMA_BF16(acc[mi][ni], Ah[mi], Bh[ni]);
                MMA_BF16(acc[mi][ni], Ah[mi], Bl[ni]);
                MMA_BF16(acc[mi][ni], Al[mi], Bh[ni]);
            }
    }

    const int g = lane >> 2, t = lane & 3;
#pragma unroll
    for (int mi = 0; mi < 4; mi++) {
        const int q = qt * 128 + wm * 64 + mi * 16 + g;
#pragma unroll
        for (int ni = 0; ni < 4; ni++) {
            const int kc = kt * 128 + wn * 32 + ni * 8 + 2 * t;
            float2 o0, o1;
            o0.x = (kc     <= q    ) ? acc[mi][ni][0] * 0.125f : NEGF;
            o0.y = (kc + 1 <= q    ) ? acc[mi][ni][1] * 0.125f : NEGF;
            o1.x = (kc     <= q + 8) ? acc[mi][ni][2] * 0.125f : NEGF;
            o1.y = (kc + 1 <= q + 8) ? acc[mi][ni][3] * 0.125f : NEGF;
            *(float2*)(S + sbase + (size_t)q * SEQ + kc)       = o0;
            *(float2*)(S + sbase + (size_t)(q + 8) * SEQ + kc) = o1;
        }
    }
}

// ============ causal softmax: row q, reads k<=q, writes P hi/lo up to tile bound
__global__ __launch_bounds__(256, 1)
void softmax_causal_kernel(const float* __restrict__ S,
                           __nv_bfloat16* __restrict__ Ph, __nv_bfloat16* __restrict__ Pl)
{
    const int q = blockIdx.x, bh = blockIdx.y;
    const int tid = threadIdx.x, warp = tid >> 5, lane = tid & 31;
    const float* row = S + ((size_t)bh * SEQ + q) * SEQ;
    const int len = q + 1;
    const int bound = ((q >> 7) + 1) << 7;

    float m = -INFINITY;
    for (int k = tid; k < len; k += 256) m = fmaxf(m, row[k]);
#pragma unroll
    for (int o = 16; o > 0; o >>= 1) m = fmaxf(m, __shfl_xor_sync(~0u, m, o));
    __shared__ float smax[8], ssum[8];
    if (lane == 0) smax[warp] = m;
    __syncthreads();
    m = smax[0];
#pragma unroll
    for (int w = 1; w < 8; w++) m = fmaxf(m, smax[w]);

    float sum = 0.f;
    for (int k = tid; k < len; k += 256) sum += expf(row[k] - m);
#pragma unroll
    for (int o = 16; o > 0; o >>= 1) sum += __shfl_xor_sync(~0u, sum, o);
    if (lane == 0) ssum[warp] = sum;
    __syncthreads();
    sum = ssum[0];
#pragma unroll
    for (int w = 1; w < 8; w++) sum += ssum[w];
    const float inv = 1.f / sum;

    __nv_bfloat16* ph = Ph + ((size_t)bh * SEQ + q) * SEQ;
    __nv_bfloat16* pl = Pl + ((size_t)bh * SEQ + q) * SEQ;
    for (int k = tid; k < bound; k += 256) {
        float p = (k < len) ? expf(row[k] - m) * inv : 0.f;
        __nv_bfloat16 h = __float2bfloat16(p);
        ph[k] = h;
        pl[k] = __float2bfloat16(p - __bfloat162float(h));
    }
}

// ============ keys softmax (512 cols) -> hi/lo ================================
__global__ __launch_bounds__(256, 1)
void softmax_keys_kernel(const float* __restrict__ src,
                         __nv_bfloat16* __restrict__ Kh, __nv_bfloat16* __restrict__ Kl)
{
    const int row = blockIdx.x;
    const int tid = threadIdx.x, warp = tid >> 5, lane = tid & 31;
    const float* p = src + (size_t)row * DMODEL;
    float v[2];
    float m = -INFINITY;
#pragma unroll
    for (int i = 0; i < 2; i++) { v[i] = p[tid + i * 256]; m = fmaxf(m, v[i]); }
#pragma unroll
    for (int o = 16; o > 0; o >>= 1) m = fmaxf(m, __shfl_xor_sync(~0u, m, o));
    __shared__ float smax[8], ssum[8];
    if (lane == 0) smax[warp] = m;
    __syncthreads();
    m = smax[0];
#pragma unroll
    for (int w = 1; w < 8; w++) m = fmaxf(m, smax[w]);
    float sum = 0.f;
#pragma unroll
    for (int i = 0; i < 2; i++) { v[i] = expf(v[i] - m); sum += v[i]; }
#pragma unroll
    for (int o = 16; o > 0; o >>= 1) sum += __shfl_xor_sync(~0u, sum, o);
    if (lane == 0) ssum[warp] = sum;
    __syncthreads();
    sum = ssum[0];
#pragma unroll
    for (int w = 1; w < 8; w++) sum += ssum[w];
    const float inv = 1.f / sum;
#pragma unroll
    for (int i = 0; i < 2; i++) {
        float pv = v[i] * inv;
        __nv_bfloat16 h = __float2bfloat16(pv);
        Kh[(size_t)row * DMODEL + tid + i * 256] = h;
        Kl[(size_t)row * DMODEL + tid + i * 256] = __float2bfloat16(pv - __bfloat162float(h));
    }
}

// ============ V^T convert ======================================================
__global__ void vt_convert_kernel(const float* __restrict__ V,
                                  __nv_bfloat16* __restrict__ Hi,
                                  __nv_bfloat16* __restrict__ Lo)
{
    __shared__ float t[32][33];
    const int k0 = blockIdx.x * 32, d0 = blockIdx.y * 32, bh = blockIdx.z;
    const int b = bh >> 3, h = bh & 7;
    const int tx = threadIdx.x & 31, ty = threadIdx.x >> 5;
#pragma unroll
    for (int j = 0; j < 32; j += 8)
        t[ty + j][tx] = V[((size_t)(b * SEQ + k0 + ty + j) * DMODEL) + h * HD + d0 + tx];
    __syncthreads();
#pragma unroll
    for (int j = 0; j < 32; j += 8) {
        float v = t[tx][ty + j];
        __nv_bfloat16 hi = __float2bfloat16(v);
        const size_t o = ((size_t)bh * HD + d0 + ty + j) * SEQ + k0 + tx;
        Hi[o] = hi;
        Lo[o] = __float2bfloat16(v - __bfloat162float(hi));
    }
}

// ============ attention output: O = P @ V (pipelined, pre-split) ==============
__global__ __launch_bounds__(256, 1)
void attn_out_mma(const __nv_bfloat16* __restrict__ Ph, const __nv_bfloat16* __restrict__ Pl,
                  const __nv_bfloat16* __restrict__ Vth, const __nv_bfloat16* __restrict__ Vtl,
                  __nv_bfloat16* __restrict__ Oh, __nv_bfloat16* __restrict__ Ol)
{
    const int qt = blockIdx.x, bh = blockIdx.y;
    const int b = bh >> 3, h = bh & 7;
    const int tid = threadIdx.x;
    const size_t pbase = (size_t)bh * SEQ * SEQ;
    const int nch = (qt + 1) * 2;

    extern __shared__ char smem[];
    const int seg = tid & 7, r0 = tid >> 3;   // 0..31

    auto load_chunk = [&](int kc, int s) {
        char* base = smem + s * AO_STAGE;
        const size_t kk = (size_t)kc * 64 + seg * 8;
#pragma unroll
        for (int it = 0; it < 4; it++) {
            const int r = r0 + it * 32;
            const uint32_t dst = smem_u32(base + (r * LDP + seg * 8) * 2);
            cp16(dst,        Ph + pbase + (size_t)(qt * 128 + r) * SEQ + kk);
            cp16(dst + T128, Pl + pbase + (size_t)(qt * 128 + r) * SEQ + kk);
        }
#pragma unroll
        for (int it = 0; it < 2; it++) {
            const int r = r0 + it * 32;
            const uint32_t dst = smem_u32(base + 2 * T128 + (r * LDP + seg * 8) * 2);
            cp16(dst,       Vth + ((size_t)bh * HD + r) * SEQ + kk);
            cp16(dst + T64, Vtl + ((size_t)bh * HD + r) * SEQ + kk);
        }
        cp_commit();
    };

    load_chunk(0, 0);

    float acc[2][4][4];
#pragma unroll
    for (int i = 0; i < 2; i++)
#pragma unroll
        for (int j = 0; j < 4; j++)
#pragma unroll
            for (int c = 0; c < 4; c++) acc[i][j][c] = 0.f;

    const int lane = tid & 31, wid = tid >> 5;
    const int wm = wid >> 1, wn = wid & 1;
    const int lm_r = (lane & 7) + ((lane >> 3) & 1) * 8;
    const int lm_c = ((lane >> 4) & 1) * 8;
    const int lb_r = (lane & 7) + ((lane >> 4) & 1) * 8;
    const int lb_c = ((lane >> 3) & 1) * 8;

    for (int kc = 0; kc < nch; kc++) {
        const int s = kc & 1;
        cp_wait0();
        __syncthreads();
        if (kc + 1 < nch) load_chunk(kc + 1, s ^ 1);

        const __nv_bfloat16* sPh = (const __nv_bfloat16*)(smem + s * AO_STAGE);
        const __nv_bfloat16* sPl = (const __nv_bfloat16*)((char*)sPh + T128);
        const __nv_bfloat16* sVh = (const __nv_bfloat16*)((char*)sPh + 2 * T128);
        const __nv_bfloat16* sVl = (const __nv_bfloat16*)((char*)sPh + 2 * T128 + T64);

#pragma unroll
        for (int ks = 0; ks < 4; ks++) {
            const int k0 = ks * 16;
            uint32_t Ah[2][4], Al[2][4], Bh[4][2], Bl[4][2];
#pragma unroll
            for (int mi = 0; mi < 2; mi++) {
                const int r = wm * 32 + mi * 16 + lm_r;
                LDMX4(Ah[mi][0], Ah[mi][1], Ah[mi][2], Ah[mi][3], smem_u32(sPh + r * LDP + k0 + lm_c));
                LDMX4(Al[mi][0], Al[mi][1], Al[mi][2], Al[mi][3], smem_u32(sPl + r * LDP + k0 + lm_c));
            }
#pragma unroll
            for (int nio = 0; nio < 2; nio++) {
                const int r = wn * 32 + nio * 16 + lb_r;
                LDMX4(Bh[2*nio][0], Bh[2*nio][1], Bh[2*nio+1][0], Bh[2*nio+1][1],
                      smem_u32(sVh + r * LDP + k0 + lb_c));
                LDMX4(Bl[2*nio][0], Bl[2*nio][1], Bl[2*nio+1][0], Bl[2*nio+1][1],
                      smem_u32(sVl + r * LDP + k0 + lb_c));
            }
#pragma unroll
            for (int mi = 0; mi < 2; mi++)
#pragma unroll
                for (int ni = 0; ni < 4; ni++) {
                    MMA_BF16(acc[mi][ni], Ah[mi], Bh[ni]);
                    MMA_BF16(acc[mi][ni], Ah[mi], Bl[ni]);
                    MMA_BF16(acc[mi][ni], Al[mi], Bh[ni]);
                }
        }
    }

    const int g = lane >> 2, t = lane & 3;
#pragma unroll
    for (int mi = 0; mi < 2; mi++) {
        const int q = qt * 128 + wm * 32 + mi * 16 + g;
#pragma unroll
        for (int ni = 0; ni < 4; ni++) {
            const int d = wn * 32 + ni * 8 + 2 * t;
            const size_t o0 = ((size_t)(b * SEQ + q) * DMODEL) + h * HD + d;
            const size_t o1 = ((size_t)(b * SEQ + q + 8) * DMODEL) + h * HD + d;
            float v00 = acc[mi][ni][0], v01 = acc[mi][ni][1];
            float v10 = acc[mi][ni][2], v11 = acc[mi][ni][3];
            __nv_bfloat16 h00 = __float2bfloat16(v00), h01 = __float2bfloat16(v01);
            __nv_bfloat16 h10 = __float2bfloat16(v10), h11 = __float2bfloat16(v11);
            *(uint32_t*)(Oh + o0) = pack2(h00, h01);
            *(uint32_t*)(Oh + o1) = pack2(h10, h11);
            *(uint32_t*)(Ol + o0) = pack2(__float2bfloat16(v00 - __bfloat162float(h00)),
                                          __float2bfloat16(v01 - __bfloat162float(h01)));
            *(uint32_t*)(Ol + o1) = pack2(__float2bfloat16(v10 - __bfloat162float(h10)),
                                          __float2bfloat16(v11 - __bfloat162float(h11)));
        }
    }
}

// ============ weight transpose + split ========================================
__global__ void transpose_convert_kernel(const float* __restrict__ W,
                                         __nv_bfloat16* __restrict__ Hi,
                                         __nv_bfloat16* __restrict__ Lo, int K, int N)
{
    __shared__ float t[32][33];
    const int k0 = blockIdx.y * 32, n0 = blockIdx.x * 32;
    const int tx = threadIdx.x & 31, ty = threadIdx.x >> 5;
#pragma unroll
    for (int j = 0; j < 32; j += 8)
        t[ty + j][tx] = W[(size_t)(k0 + ty + j) * N + n0 + tx];
    __syncthreads();
#pragma unroll
    for (int j = 0; j < 32; j += 8) {
        float v = t[tx][ty + j];
        __nv_bfloat16 h = __float2bfloat16(v);
        Hi[(size_t)(n0 + ty + j) * K + k0 + tx] = h;
        Lo[(size_t)(n0 + ty + j) * K + k0 + tx] = __float2bfloat16(v - __bfloat162float(h));
    }
}

// ============ elementwise split ===============================================
__global__ void split_kernel(const float* __restrict__ in,
                             __nv_bfloat16* __restrict__ hi, __nv_bfloat16* __restrict__ lo)
{
    const int i = blockIdx.x * 256 + threadIdx.x;
    float4 v = ((const float4*)in)[i];
    uint2 h, l;
    split4(v, h, l);
    ((uint2*)hi)[i] = h;
    ((uint2*)lo)[i] = l;
}

// ============ residual + LayerNorm, emits fp32 + hi/lo ========================
__global__ void ln_kernel(const float* __restrict__ xin, const float* __restrict__ res,
                          const float* __restrict__ scale, const float* __restrict__ bias,
                          float* __restrict__ outf,
                          __nv_bfloat16* __restrict__ outh, __nv_bfloat16* __restrict__ outl)
{
    const int row = blockIdx.x;
    const int tid = threadIdx.x;
    float4 v = ((const float4*)(xin + (size_t)row * DMODEL))[tid];
    if (res) {
        float4 r = ((const float4*)(res + (size_t)row * DMODEL))[tid];
        v.x += r.x; v.y += r.y; v.z += r.z; v.w += r.w;
    }
    float s  = v.x + v.y + v.z + v.w;
    float sq = v.x * v.x + v.y * v.y + v.z * v.z + v.w * v.w;
#pragma unroll
    for (int o = 16; o > 0; o >>= 1) {
        s  += __shfl_xor_sync(~0u, s,  o);
        sq += __shfl_xor_sync(~0u, sq, o);
    }
    __shared__ float ss[4], sqs[4];
    const int warp = tid >> 5, lane = tid & 31;
    if (lane == 0) { ss[warp] = s; sqs[warp] = sq; }
    __syncthreads();
    float S  = ss[0]  + ss[1]  + ss[2]  + ss[3];
    float SQ = sqs[0] + sqs[1] + sqs[2] + sqs[3];
    float mean = S * (1.f / DMODEL);
    float var  = SQ * (1.f / DMODEL) - mean * mean;
    float rs   = rsqrtf(var + 1e-6f);
    float4 sc4 = ((const float4*)scale)[tid];
    float4 bi4 = ((const float4*)bias)[tid];
    float4 o;
    o.x = (v.x - mean) * rs * sc4.x + bi4.x;
    o.y = (v.y - mean) * rs * sc4.y + bi4.y;
    o.z = (v.z - mean) * rs * sc4.z + bi4.z;
    o.w = (v.w - mean) * rs * sc4.w + bi4.w;
    if (outf) ((float4*)(outf + (size_t)row * DMODEL))[tid] = o;
    uint2 h, l;
    split4(o, h, l);
    ((uint2*)(outh + (size_t)row * DMODEL))[tid] = h;
    ((uint2*)(outl + (size_t)row * DMODEL))[tid] = l;
}

// ============ cosine-score argmax + gather ====================================
__global__ void score_argmax_kernel(const float* __restrict__ Vs, const float* __restrict__ x,
                                    const float* __restrict__ Ss, float* __restrict__ vout,
                                    float* __restrict__ sout)
{
    const int n = blockIdx.x;
    const int tid = threadIdx.x;
    const int warp = tid >> 5, lane = tid & 31;
    __shared__ float xs[32];
    __shared__ float wbest[8];
    __shared__ int   widx[8];
    if (tid < 32) xs[tid] = x[(size_t)n * OUTD + tid];
    __syncthreads();
    const float xv = xs[lane];
    const float* vrow = Vs + (size_t)n * NSLOTS * OUTD;

    float best = -INFINITY;
    int   bidx = 0;
    for (int k = warp; k < NSLOTS; k += 8) {
        float v = vrow[k * OUTD + lane];
        float d = v * xv;
        float s = v * v;
#pragma unroll
        for (int o = 16; o > 0; o >>= 1) {
            d += __shfl_xor_sync(~0u, d, o);
            s += __shfl_xor_sync(~0u, s, o);
        }
        float sc = d / sqrtf(s);
        if (sc > best) { best = sc; bidx = k; }
    }
    if (lane == 0) { wbest[warp] = best; widx[warp] = bidx; }
    __syncthreads();
    if (tid == 0) {
        float b = wbest[0]; int bi = widx[0];
        for (int w = 1; w < 8; w++)
            if (wbest[w] > b || (wbest[w] == b && widx[w] < bi)) { b = wbest[w]; bi = widx[w]; }
        widx[0] = bi;
    }
    __syncthreads();
    const int idx = widx[0];
    if (tid < 32) vout[(size_t)n * OUTD + tid] = vrow[idx * OUTD + tid];
    if (tid == 0) sout[n] = Ss[(size_t)n * NSLOTS + idx];
}

// ---------------- host-side wrapper ----------------
struct Bufs {
    __nv_bfloat16 *bthi, *btlo;
};
static void tc_gemm(const __nv_bfloat16* Ah, const __nv_bfloat16* Al,
                    const float* W, const float* bias,
                    float* Cf, __nv_bfloat16* Chi, __nv_bfloat16* Clo,
                    int M, int N, int K, int relu, const Bufs& bf)
{
    transpose_convert_kernel<<<dim3(N / 32, K / 32), 256>>>(W, bf.bthi, bf.btlo, K, N);
    gemm_bb_kernel<<<dim3(N / 128, M / 128), 512, GEMM_SMEM>>>(
        Ah, Al, bf.bthi, bf.btlo, bias, Cf, Chi, Clo, M, N, K, relu);
}

extern "C" void kernel_launch(void* const* d_in, const int* in_sizes, int n_in,
                              void* d_out, int out_size)
{
    const float* s_in  = (const float*)d_in[0];
    const float* x_in  = (const float*)d_in[1];
    const float* t_in  = (const float*)d_in[2];
    const float* Wq    = (const float*)d_in[3];
    const float* Wk    = (const float*)d_in[4];
    const float* Wv    = (const float*)d_in[5];
    const float* Wo    = (const float*)d_in[6];
    const float* cWv   = (const float*)d_in[9];
    const float* cWo   = (const float*)d_in[10];
    const float* ln1_s = (const float*)d_in[11];
    const float* ln1_b = (const float*)d_in[12];
    const float* ln2_s = (const float*)d_in[13];
    const float* ln2_b = (const float*)d_in[14];
    const float* ln3_s = (const float*)d_in[15];
    const float* ln3_b = (const float*)d_in[16];
    const float* W1    = (const float*)d_in[17];
    const float* b1    = (const float*)d_in[18];
    const float* W2    = (const float*)d_in[19];
    const float* b2    = (const float*)d_in[20];
    const float* lnf_s = (const float*)d_in[21];
    const float* lnf_b = (const float*)d_in[22];
    const float* Wout  = (const float*)d_in[23];
    const float* bout  = (const float*)d_in[24];
    const float* W_vs  = (const float*)d_in[25];
    const float* b_vs  = (const float*)d_in[26];
    const float* W_ss  = (const float*)d_in[27];
    const float* b_ss  = (const float*)d_in[28];
    float* out = (float*)d_out;

    float *dec, *vb, *tmp2, *sc, *vs;
    __nv_bfloat16 *dech, *decl, *qbh, *qbl, *kbh, *kbl, *obh, *obl, *th, *tl;
    __nv_bfloat16 *ffh, *ffl, *keysh, *keysl, *ph, *pl, *vthi, *vtlo;
    Bufs bf;
    cudaGetSymbolAddress((void**)&dec,  g_dec);
    cudaGetSymbolAddress((void**)&vb,   g_vb);
    cudaGetSymbolAddress((void**)&tmp2, g_tmp2);
    cudaGetSymbolAddress((void**)&sc,   g_sc);
    cudaGetSymbolAddress((void**)&vs,   g_vs);
    cudaGetSymbolAddress((void**)&dech, g_dech);
    cudaGetSymbolAddress((void**)&decl, g_decl);
    cudaGetSymbolAddress((void**)&qbh,  g_qbh);
    cudaGetSymbolAddress((void**)&qbl,  g_qbl);
    cudaGetSymbolAddress((void**)&kbh,  g_kbh);
    cudaGetSymbolAddress((void**)&kbl,  g_kbl);
    cudaGetSymbolAddress((void**)&obh,  g_obh);
    cudaGetSymbolAddress((void**)&obl,  g_obl);
    cudaGetSymbolAddress((void**)&th,   g_th);
    cudaGetSymbolAddress((void**)&tl,   g_tl);
    cudaGetSymbolAddress((void**)&ffh,  g_ffh);
    cudaGetSymbolAddress((void**)&ffl,  g_ffl);
    cudaGetSymbolAddress((void**)&keysh,g_keysh);
    cudaGetSymbolAddress((void**)&keysl,g_keysl);
    cudaGetSymbolAddress((void**)&ph,   g_ph);
    cudaGetSymbolAddress((void**)&pl,   g_pl);
    cudaGetSymbolAddress((void**)&vthi, g_vthi);
    cudaGetSymbolAddress((void**)&vtlo, g_vtlo);
    cudaGetSymbolAddress((void**)&bf.bthi, g_bthi);
    cudaGetSymbolAddress((void**)&bf.btlo, g_btlo);

    cudaFuncSetAttribute(gemm_bb_kernel,  cudaFuncAttributeMaxDynamicSharedMemorySize, GEMM_SMEM);
    cudaFuncSetAttribute(attn_scores_mma, cudaFuncAttributeMaxDynamicSharedMemorySize, ASC_SMEM);
    cudaFuncSetAttribute(attn_out_mma,    cudaFuncAttributeMaxDynamicSharedMemorySize, AO_SMEM);

    cudaMemcpyAsync(dec, s_in, sizeof(float) * NTOK * DMODEL, cudaMemcpyDeviceToDevice);
    split_kernel<<<NTOK * DMODEL / 1024, 256>>>(s_in, dech, decl);
    split_kernel<<<NTOK * DMODEL / 1024, 256>>>(t_in, th, tl);

    for (int l = 0; l < 2; l++) {
        const size_t wo = (size_t)l * DMODEL * DMODEL;
        // causal self-attention
        tc_gemm(dech, decl, Wq + wo, nullptr, nullptr, qbh, qbl, NTOK, DMODEL, DMODEL, 0, bf);
        tc_gemm(dech, decl, Wk + wo, nullptr, nullptr, kbh, kbl, NTOK, DMODEL, DMODEL, 0, bf);
        tc_gemm(dech, decl, Wv + wo, nullptr, vb, nullptr, nullptr, NTOK, DMODEL, DMODEL, 0, bf);
        attn_scores_mma<<<dim3(8, 8, 64), 256, ASC_SMEM>>>(qbh, qbl, kbh, kbl, sc);
        softmax_causal_kernel<<<dim3(SEQ, 64), 256>>>(sc, ph, pl);
        vt_convert_kernel<<<dim3(32, 2, 64), 256>>>(vb, vthi, vtlo);
        attn_out_mma<<<dim3(8, 64), 256, AO_SMEM>>>(ph, pl, vthi, vtlo, obh, obl);
        tc_gemm(obh, obl, Wo + wo, nullptr, tmp2, nullptr, nullptr, NTOK, DMODEL, DMODEL, 0, bf);
        ln_kernel<<<NTOK, 128>>>(dec, tmp2, ln1_s + l * DMODEL, ln1_b + l * DMODEL, dec, dech, decl);
        // cross-attention (eye mask -> o = (t @ cWv) @ cWo)
        tc_gemm(th, tl, cWv + wo, nullptr, nullptr, obh, obl, NTOK, DMODEL, DMODEL, 0, bf);
        tc_gemm(obh, obl, cWo + wo, nullptr, tmp2, nullptr, nullptr, NTOK, DMODEL, DMODEL, 0, bf);
        ln_kernel<<<NTOK, 128>>>(dec, tmp2, ln2_s + l * DMODEL, ln2_b + l * DMODEL, dec, dech, decl);
        // FFN
        tc_gemm(dech, decl, W1 + (size_t)l * DMODEL * FFDIM, b1 + (size_t)l * FFDIM,
                nullptr, ffh, ffl, NTOK, FFDIM, DMODEL, 1, bf);
        tc_gemm(ffh, ffl, W2 + (size_t)l * FFDIM * DMODEL, b2 + (size_t)l * DMODEL,
                tmp2, nullptr, nullptr, NTOK, DMODEL, FFDIM, 0, bf);
        ln_kernel<<<NTOK, 128>>>(dec, tmp2, ln3_s + l * DMODEL, ln3_b + l * DMODEL, dec, dech, decl);
    }

    // final head
    ln_kernel<<<NTOK, 128>>>(dec, nullptr, lnf_s, lnf_b, nullptr, qbh, qbl);
    tc_gemm(qbh, qbl, Wout, bout, tmp2, nullptr, nullptr, NTOK, DMODEL, DMODEL, 0, bf);  // logits
    softmax_keys_kernel<<<NTOK, 256>>>(tmp2, keysh, keysl);

    float* out_v  = out;
    float* out_s  = out + 262144;
    float* out_ss = out + 262144 + 8192;

    tc_gemm(keysh, keysl, W_ss, b_ss, out_ss, nullptr, nullptr, NTOK, NSLOTS, DMODEL, 0, bf);
    tc_gemm(keysh, keysl, W_vs, b_vs, vs, nullptr, nullptr, NTOK, NSLOTS * OUTD, DMODEL, 0, bf);
    score_argmax_kernel<<<NTOK, 256>>>(vs, x_in, out_ss, out_v, out_s);
}

// round 6
// speedup vs baseline: 2.2859x; 1.0734x over previous
#include <cuda_runtime.h>
#include <cuda_bf16.h>
#include <math.h>
#include <stdint.h>

#define NTOK   8192
#define DMODEL 512
#define HEADS  8
#define HD     64
#define SEQ    1024
#define FFDIM  2048
#define NSLOTS 512
#define OUTD   32
#define NEGF   (-3.4028234663852886e38f)

// ---------------- static scratch ----------------
__device__ float g_dec [NTOK * DMODEL];
__device__ float g_vb  [NTOK * DMODEL];
__device__ float g_tmp2[NTOK * DMODEL];
__device__ float g_sc  [(size_t)64 * SEQ * SEQ];
__device__ float g_vs  [(size_t)NTOK * NSLOTS * OUTD];
__device__ unsigned long long g_best[NTOK];
__device__ __nv_bfloat16 g_dech[NTOK * DMODEL], g_decl[NTOK * DMODEL];
__device__ __nv_bfloat16 g_qbh [NTOK * DMODEL], g_qbl [NTOK * DMODEL];
__device__ __nv_bfloat16 g_kbh [NTOK * DMODEL], g_kbl [NTOK * DMODEL];
__device__ __nv_bfloat16 g_obh [NTOK * DMODEL], g_obl [NTOK * DMODEL];
__device__ __nv_bfloat16 g_th  [NTOK * DMODEL], g_tl  [NTOK * DMODEL];
__device__ __nv_bfloat16 g_ffh [NTOK * FFDIM],  g_ffl [NTOK * FFDIM];
__device__ __nv_bfloat16 g_keysh[NTOK * DMODEL], g_keysl[NTOK * DMODEL];
__device__ __nv_bfloat16 g_ph[(size_t)64 * SEQ * SEQ], g_pl[(size_t)64 * SEQ * SEQ];
__device__ __nv_bfloat16 g_vthi[64 * HD * SEQ], g_vtlo[64 * HD * SEQ];
__device__ __nv_bfloat16 g_bthi[8388608], g_btlo[8388608];
__device__ __nv_bfloat16 g_cvh[2 * DMODEL * DMODEL], g_cvl[2 * DMODEL * DMODEL];

__device__ __forceinline__ uint32_t smem_u32(const void* p) {
    uint32_t a;
    asm("{ .reg .u64 t; cvta.to.shared.u64 t, %1; cvt.u32.u64 %0, t; }" : "=r"(a) : "l"(p));
    return a;
}
__device__ __forceinline__ uint32_t pack2(__nv_bfloat16 a, __nv_bfloat16 b) {
    return (uint32_t)__bfloat16_as_ushort(a) | ((uint32_t)__bfloat16_as_ushort(b) << 16);
}
__device__ __forceinline__ void cp16(uint32_t dst, const void* src) {
    asm volatile("cp.async.cg.shared.global [%0], [%1], 16;" :: "r"(dst), "l"(src) : "memory");
}
__device__ __forceinline__ void cp_commit() {
    asm volatile("cp.async.commit_group;" ::: "memory");
}
__device__ __forceinline__ void cp_wait0() {
    asm volatile("cp.async.wait_group 0;" ::: "memory");
}
__device__ __forceinline__ void split4(float4 v, uint2& hi, uint2& lo) {
    __nv_bfloat16 hx = __float2bfloat16(v.x), hy = __float2bfloat16(v.y);
    __nv_bfloat16 hz = __float2bfloat16(v.z), hw = __float2bfloat16(v.w);
    __nv_bfloat16 lx = __float2bfloat16(v.x - __bfloat162float(hx));
    __nv_bfloat16 ly = __float2bfloat16(v.y - __bfloat162float(hy));
    __nv_bfloat16 lz = __float2bfloat16(v.z - __bfloat162float(hz));
    __nv_bfloat16 lw = __float2bfloat16(v.w - __bfloat162float(hw));
    hi = make_uint2(pack2(hx, hy), pack2(hz, hw));
    lo = make_uint2(pack2(lx, ly), pack2(lz, lw));
}
// float -> order-preserving uint; key = (ordered score << 32) | ~slot  (ties -> smaller slot)
__device__ __forceinline__ unsigned long long score_key(float s, int slot) {
    unsigned int u = __float_as_uint(s);
    u = (u & 0x80000000u) ? ~u : (u | 0x80000000u);
    return ((unsigned long long)u << 32) | (unsigned int)(~slot);
}

#define LDMX4(r0, r1, r2, r3, addr) \
    asm volatile("ldmatrix.sync.aligned.m8n8.x4.shared.b16 {%0,%1,%2,%3}, [%4];" \
        : "=r"(r0), "=r"(r1), "=r"(r2), "=r"(r3) : "r"(addr))

#define MMA_BF16(c, a, b) \
    asm volatile("mma.sync.aligned.m16n8k16.row.col.f32.bf16.bf16.f32 " \
        "{%0,%1,%2,%3}, {%4,%5,%6,%7}, {%8,%9}, {%0,%1,%2,%3};" \
        : "+f"((c)[0]), "+f"((c)[1]), "+f"((c)[2]), "+f"((c)[3]) \
        : "r"((a)[0]), "r"((a)[1]), "r"((a)[2]), "r"((a)[3]), "r"((b)[0]), "r"((b)[1]))

#define LDP 72
#define T128 (128 * LDP * 2)
#define T64  (64 * LDP * 2)
#define GEMM_STAGE (4 * T128)
#define GEMM_SMEM  (2 * GEMM_STAGE)
#define ASC_SMEM   (4 * T128)
#define AO_STAGE   (2 * T128 + 2 * T64)
#define AO_SMEM    (2 * AO_STAGE)

// ============ split-bf16 HMMA GEMM + optional fused slot-scoring ==============
__global__ __launch_bounds__(512, 1)
void gemm_bb_kernel(const __nv_bfloat16* __restrict__ Ahi, const __nv_bfloat16* __restrict__ Alo,
                    const __nv_bfloat16* __restrict__ Bhi, const __nv_bfloat16* __restrict__ Blo,
                    const float* __restrict__ bias,
                    float* __restrict__ Cf, __nv_bfloat16* __restrict__ Chi,
                    __nv_bfloat16* __restrict__ Clo,
                    int M, int N, int K, int relu,
                    const float* __restrict__ xsc, unsigned long long* __restrict__ best)
{
    extern __shared__ char smem[];
    const int tid  = threadIdx.x;
    const int lane = tid & 31, wid = tid >> 5;
    const int wm = wid >> 2, wn = wid & 3;
    const size_t brow = (size_t)blockIdx.y * 128;
    const size_t bcol = (size_t)blockIdx.x * 128;
    const int seg = tid & 7, r0 = tid >> 3;

    const int NP = K >> 6;

    auto load_panel = [&](int p, int s) {
        char* base = smem + s * GEMM_STAGE;
        const size_t ka = (size_t)p * 64 + seg * 8;
#pragma unroll
        for (int hf = 0; hf < 2; hf++) {
            const int r = r0 + hf * 64;
            const uint32_t dst = smem_u32(base + (r * LDP + seg * 8) * 2);
            cp16(dst,            Ahi + (brow + r) * K + ka);
            cp16(dst + T128,     Alo + (brow + r) * K + ka);
            cp16(dst + 2 * T128, Bhi + (bcol + r) * K + ka);
            cp16(dst + 3 * T128, Blo + (bcol + r) * K + ka);
        }
        cp_commit();
    };

    load_panel(0, 0);

    float acc[2][4][4];
#pragma unroll
    for (int i = 0; i < 2; i++)
#pragma unroll
        for (int j = 0; j < 4; j++)
#pragma unroll
            for (int c = 0; c < 4; c++) acc[i][j][c] = 0.f;

    const int lm_r = (lane & 7) + ((lane >> 3) & 1) * 8;
    const int lm_c = ((lane >> 4) & 1) * 8;
    const int lb_r = (lane & 7) + ((lane >> 4) & 1) * 8;
    const int lb_c = ((lane >> 3) & 1) * 8;

    for (int p = 0; p < NP; p++) {
        const int s = p & 1;
        cp_wait0();
        __syncthreads();
        if (p + 1 < NP) load_panel(p + 1, s ^ 1);

        const __nv_bfloat16* sAh = (const __nv_bfloat16*)(smem + s * GEMM_STAGE);
        const __nv_bfloat16* sAl = (const __nv_bfloat16*)((char*)sAh + T128);
        const __nv_bfloat16* sBh = (const __nv_bfloat16*)((char*)sAh + 2 * T128);
        const __nv_bfloat16* sBl = (const __nv_bfloat16*)((char*)sAh + 3 * T128);

#pragma unroll
        for (int ks = 0; ks < 4; ks++) {
            const int k0 = ks * 16;
            uint32_t Ah[2][4], Al[2][4], Bh[4][2], Bl[4][2];
#pragma unroll
            for (int mi = 0; mi < 2; mi++) {
                const int r = wm * 32 + mi * 16 + lm_r;
                LDMX4(Ah[mi][0], Ah[mi][1], Ah[mi][2], Ah[mi][3], smem_u32(sAh + r * LDP + k0 + lm_c));
                LDMX4(Al[mi][0], Al[mi][1], Al[mi][2], Al[mi][3], smem_u32(sAl + r * LDP + k0 + lm_c));
            }
#pragma unroll
            for (int nio = 0; nio < 2; nio++) {
                const int r = wn * 32 + nio * 16 + lb_r;
                LDMX4(Bh[2*nio][0], Bh[2*nio][1], Bh[2*nio+1][0], Bh[2*nio+1][1],
                      smem_u32(sBh + r * LDP + k0 + lb_c));
                LDMX4(Bl[2*nio][0], Bl[2*nio][1], Bl[2*nio+1][0], Bl[2*nio+1][1],
                      smem_u32(sBl + r * LDP + k0 + lb_c));
            }
            // pass-major ordering: 8 independent mmas between same-acc reuses
#pragma unroll
            for (int mi = 0; mi < 2; mi++)
#pragma unroll
                for (int ni = 0; ni < 4; ni++) MMA_BF16(acc[mi][ni], Ah[mi], Bh[ni]);
#pragma unroll
            for (int mi = 0; mi < 2; mi++)
#pragma unroll
                for (int ni = 0; ni < 4; ni++) MMA_BF16(acc[mi][ni], Ah[mi], Bl[ni]);
#pragma unroll
            for (int mi = 0; mi < 2; mi++)
#pragma unroll
                for (int ni = 0; ni < 4; ni++) MMA_BF16(acc[mi][ni], Al[mi], Bh[ni]);
        }
    }

    // epilogue
    const int g = lane >> 2, t = lane & 3;
#pragma unroll
    for (int mi = 0; mi < 2; mi++) {
        const size_t rm = brow + wm * 32 + mi * 16 + g;
        float dA = 0.f, sA = 0.f, dB = 0.f, sB = 0.f;
#pragma unroll
        for (int ni = 0; ni < 4; ni++) {
            const size_t cn = bcol + wn * 32 + ni * 8 + 2 * t;
            float b0 = 0.f, b1 = 0.f;
            if (bias) { b0 = bias[cn]; b1 = bias[cn + 1]; }
            float v00 = acc[mi][ni][0] + b0, v01 = acc[mi][ni][1] + b1;
            float v10 = acc[mi][ni][2] + b0, v11 = acc[mi][ni][3] + b1;
            if (relu) {
                v00 = fmaxf(v00, 0.f); v01 = fmaxf(v01, 0.f);
                v10 = fmaxf(v10, 0.f); v11 = fmaxf(v11, 0.f);
            }
            if (Cf) {
                *(float2*)(Cf + rm * N + cn)       = make_float2(v00, v01);
                *(float2*)(Cf + (rm + 8) * N + cn) = make_float2(v10, v11);
            }
            if (Chi) {
                __nv_bfloat16 h00 = __float2bfloat16(v00), h01 = __float2bfloat16(v01);
                __nv_bfloat16 h10 = __float2bfloat16(v10), h11 = __float2bfloat16(v11);
                *(uint32_t*)(Chi + rm * N + cn)       = pack2(h00, h01);
                *(uint32_t*)(Chi + (rm + 8) * N + cn) = pack2(h10, h11);
                *(uint32_t*)(Clo + rm * N + cn)       =
                    pack2(__float2bfloat16(v00 - __bfloat162float(h00)),
                          __float2bfloat16(v01 - __bfloat162float(h01)));
                *(uint32_t*)(Clo + (rm + 8) * N + cn) =
                    pack2(__float2bfloat16(v10 - __bfloat162float(h10)),
                          __float2bfloat16(v11 - __bfloat162float(h11)));
            }
            if (xsc) {
                const int o = ni * 8 + 2 * t;      // column within the 32-wide slot
                float xa0 = xsc[rm * OUTD + o],       xa1 = xsc[rm * OUTD + o + 1];
                float xb0 = xsc[(rm + 8) * OUTD + o], xb1 = xsc[(rm + 8) * OUTD + o + 1];
                dA += v00 * xa0 + v01 * xa1;  sA += v00 * v00 + v01 * v01;
                dB += v10 * xb0 + v11 * xb1;  sB += v10 * v10 + v11 * v11;
            }
        }
        if (xsc) {
            // reduce over the quad (t = lane bits 0..1)
#pragma unroll
            for (int m = 1; m <= 2; m <<= 1) {
                dA += __shfl_xor_sync(~0u, dA, m);
                sA += __shfl_xor_sync(~0u, sA, m);
                dB += __shfl_xor_sync(~0u, dB, m);
                sB += __shfl_xor_sync(~0u, sB, m);
            }
            if (t == 0) {
                const int slot = (int)((bcol + wn * 32) >> 5);
                atomicMax(&best[rm],     score_key(dA * rsqrtf(sA), slot));
                atomicMax(&best[rm + 8], score_key(dB * rsqrtf(sB), slot));
            }
        }
    }
}

// ============ attention scores (causal tiles only) ============================
__global__ __launch_bounds__(256, 1)
void attn_scores_mma(const __nv_bfloat16* __restrict__ Qh, const __nv_bfloat16* __restrict__ Ql,
                     const __nv_bfloat16* __restrict__ Kh, const __nv_bfloat16* __restrict__ Kl,
                     float* __restrict__ S)
{
    const int kt = blockIdx.x, qt = blockIdx.y, bh = blockIdx.z;
    if (kt > qt) return;
    const int b = bh >> 3, h = bh & 7;
    const int tid = threadIdx.x;
    const size_t sbase = (size_t)bh * SEQ * SEQ;

    extern __shared__ char smem[];
    const int seg = tid & 7, r0 = tid >> 3;
#pragma unroll
    for (int it = 0; it < 4; it++) {
        const int r = r0 + it * 32;
        const uint32_t dst = smem_u32(smem + (r * LDP + seg * 8) * 2);
        const size_t qoff = ((size_t)(b * SEQ + qt * 128 + r) * DMODEL) + h * HD + seg * 8;
        const size_t koff = ((size_t)(b * SEQ + kt * 128 + r) * DMODEL) + h * HD + seg * 8;
        cp16(dst,            Qh + qoff);
        cp16(dst + T128,     Ql + qoff);
        cp16(dst + 2 * T128, Kh + koff);
        cp16(dst + 3 * T128, Kl + koff);
    }
    cp_commit();
    cp_wait0();
    __syncthreads();

    const __nv_bfloat16* sAh = (const __nv_bfloat16*)smem;
    const __nv_bfloat16* sAl = (const __nv_bfloat16*)(smem + T128);
    const __nv_bfloat16* sBh = (const __nv_bfloat16*)(smem + 2 * T128);
    const __nv_bfloat16* sBl = (const __nv_bfloat16*)(smem + 3 * T128);

    const int lane = tid & 31, wid = tid >> 5;
    const int wm = wid >> 2, wn = wid & 3;
    const int lm_r = (lane & 7) + ((lane >> 3) & 1) * 8;
    const int lm_c = ((lane >> 4) & 1) * 8;
    const int lb_r = (lane & 7) + ((lane >> 4) & 1) * 8;
    const int lb_c = ((lane >> 3) & 1) * 8;

    float acc[4][4][4];
#pragma unroll
    for (int i = 0; i < 4; i++)
#pragma unroll
        for (int j = 0; j < 4; j++)
#pragma unroll
            for (int c = 0; c < 4; c++) acc[i][j][c] = 0.f;

#pragma unroll
    for (int ks = 0; ks < 4; ks++) {
        const int k0 = ks * 16;
        uint32_t Ah[4][4], Al[4][4], Bh[4][2], Bl[4][2];
#pragma unroll
        for (int mi = 0; mi < 4; mi++) {
            const int r = wm * 64 + mi * 16 + lm_r;
            LDMX4(Ah[mi][0], Ah[mi][1], Ah[mi][2], Ah[mi][3], smem_u32(sAh + r * LDP + k0 + lm_c));
            LDMX4(Al[mi][0], Al[mi][1], Al[mi][2], Al[mi][3], smem_u32(sAl + r * LDP + k0 + lm_c));
        }
#pragma unroll
        for (int nio = 0; nio < 2; nio++) {
            const int r = wn * 32 + nio * 16 + lb_r;
            LDMX4(Bh[2*nio][0], Bh[2*nio][1], Bh[2*nio+1][0], Bh[2*nio+1][1],
                  smem_u32(sBh + r * LDP + k0 + lb_c));
            LDMX4(Bl[2*nio][0], Bl[2*nio][1], Bl[2*nio+1][0], Bl[2*nio+1][1],
                  smem_u32(sBl + r * LDP + k0 + lb_c));
        }
#pragma unroll
        for (int mi = 0; mi < 4; mi++)
#pragma unroll
            for (int ni = 0; ni < 4; ni++) MMA_BF16(acc[mi][ni], Ah[mi], Bh[ni]);
#pragma unroll
        for (int mi = 0; mi < 4; mi++)
#pragma unroll
            for (int ni = 0; ni < 4; ni++) MMA_BF16(acc[mi][ni], Ah[mi], Bl[ni]);
#pragma unroll
        for (int mi = 0; mi < 4; mi++)
#pragma unroll
            for (int ni = 0; ni < 4; ni++) MMA_BF16(acc[mi][ni], Al[mi], Bh[ni]);
    }

    const int g = lane >> 2, t = lane & 3;
#pragma unroll
    for (int mi = 0; mi < 4; mi++) {
        const int q = qt * 128 + wm * 64 + mi * 16 + g;
#pragma unroll
        for (int ni = 0; ni < 4; ni++) {
            const int kc = kt * 128 + wn * 32 + ni * 8 + 2 * t;
            float2 o0, o1;
            o0.x = (kc     <= q    ) ? acc[mi][ni][0] * 0.125f : NEGF;
            o0.y = (kc + 1 <= q    ) ? acc[mi][ni][1] * 0.125f : NEGF;
            o1.x = (kc     <= q + 8) ? acc[mi][ni][2] * 0.125f : NEGF;
            o1.y = (kc + 1 <= q + 8) ? acc[mi][ni][3] * 0.125f : NEGF;
            *(float2*)(S + sbase + (size_t)q * SEQ + kc)       = o0;
            *(float2*)(S + sbase + (size_t)(q + 8) * SEQ + kc) = o1;
        }
    }
}

// ============ causal softmax ===================================================
__global__ __launch_bounds__(256, 1)
void softmax_causal_kernel(const float* __restrict__ S,
                           __nv_bfloat16* __restrict__ Ph, __nv_bfloat16* __restrict__ Pl)
{
    const int q = blockIdx.x, bh = blockIdx.y;
    const int tid = threadIdx.x, warp = tid >> 5, lane = tid & 31;
    const float* row = S + ((size_t)bh * SEQ + q) * SEQ;
    const int len = q + 1;
    const int bound = ((q >> 7) + 1) << 7;

    float m = -INFINITY;
    for (int k = tid; k < len; k += 256) m = fmaxf(m, row[k]);
#pragma unroll
    for (int o = 16; o > 0; o >>= 1) m = fmaxf(m, __shfl_xor_sync(~0u, m, o));
    __shared__ float smax[8], ssum[8];
    if (lane == 0) smax[warp] = m;
    __syncthreads();
    m = smax[0];
#pragma unroll
    for (int w = 1; w < 8; w++) m = fmaxf(m, smax[w]);

    float sum = 0.f;
    for (int k = tid; k < len; k += 256) sum += expf(row[k] - m);
#pragma unroll
    for (int o = 16; o > 0; o >>= 1) sum += __shfl_xor_sync(~0u, sum, o);
    if (lane == 0) ssum[warp] = sum;
    __syncthreads();
    sum = ssum[0];
#pragma unroll
    for (int w = 1; w < 8; w++) sum += ssum[w];
    const float inv = 1.f / sum;

    __nv_bfloat16* ph = Ph + ((size_t)bh * SEQ + q) * SEQ;
    __nv_bfloat16* pl = Pl + ((size_t)bh * SEQ + q) * SEQ;
    for (int k = tid; k < bound; k += 256) {
        float p = (k < len) ? expf(row[k] - m) * inv : 0.f;
        __nv_bfloat16 h = __float2bfloat16(p);
        ph[k] = h;
        pl[k] = __float2bfloat16(p - __bfloat162float(h));
    }
}

// ============ keys softmax -> hi/lo ===========================================
__global__ __launch_bounds__(256, 1)
void softmax_keys_kernel(const float* __restrict__ src,
                         __nv_bfloat16* __restrict__ Kh, __nv_bfloat16* __restrict__ Kl)
{
    const int row = blockIdx.x;
    const int tid = threadIdx.x, warp = tid >> 5, lane = tid & 31;
    const float* p = src + (size_t)row * DMODEL;
    float v[2];
    float m = -INFINITY;
#pragma unroll
    for (int i = 0; i < 2; i++) { v[i] = p[tid + i * 256]; m = fmaxf(m, v[i]); }
#pragma unroll
    for (int o = 16; o > 0; o >>= 1) m = fmaxf(m, __shfl_xor_sync(~0u, m, o));
    __shared__ float smax[8], ssum[8];
    if (lane == 0) smax[warp] = m;
    __syncthreads();
    m = smax[0];
#pragma unroll
    for (int w = 1; w < 8; w++) m = fmaxf(m, smax[w]);
    float sum = 0.f;
#pragma unroll
    for (int i = 0; i < 2; i++) { v[i] = expf(v[i] - m); sum += v[i]; }
#pragma unroll
    for (int o = 16; o > 0; o >>= 1) sum += __shfl_xor_sync(~0u, sum, o);
    if (lane == 0) ssum[warp] = sum;
    __syncthreads();
    sum = ssum[0];
#pragma unroll
    for (int w = 1; w < 8; w++) sum += ssum[w];
    const float inv = 1.f / sum;
#pragma unroll
    for (int i = 0; i < 2; i++) {
        float pv = v[i] * inv;
        __nv_bfloat16 h = __float2bfloat16(pv);
        Kh[(size_t)row * DMODEL + tid + i * 256] = h;
        Kl[(size_t)row * DMODEL + tid + i * 256] = __float2bfloat16(pv - __bfloat162float(h));
    }
}

// ============ V^T convert ======================================================
__global__ void vt_convert_kernel(const float* __restrict__ V,
                                  __nv_bfloat16* __restrict__ Hi,
                                  __nv_bfloat16* __restrict__ Lo)
{
    __shared__ float t[32][33];
    const int k0 = blockIdx.x * 32, d0 = blockIdx.y * 32, bh = blockIdx.z;
    const int b = bh >> 3, h = bh & 7;
    const int tx = threadIdx.x & 31, ty = threadIdx.x >> 5;
#pragma unroll
    for (int j = 0; j < 32; j += 8)
        t[ty + j][tx] = V[((size_t)(b * SEQ + k0 + ty + j) * DMODEL) + h * HD + d0 + tx];
    __syncthreads();
#pragma unroll
    for (int j = 0; j < 32; j += 8) {
        float v = t[tx][ty + j];
        __nv_bfloat16 hi = __float2bfloat16(v);
        const size_t o = ((size_t)bh * HD + d0 + ty + j) * SEQ + k0 + tx;
        Hi[o] = hi;
        Lo[o] = __float2bfloat16(v - __bfloat162float(hi));
    }
}

// ============ attention output: O = P @ V =====================================
__global__ __launch_bounds__(256, 1)
void attn_out_mma(const __nv_bfloat16* __restrict__ Ph, const __nv_bfloat16* __restrict__ Pl,
                  const __nv_bfloat16* __restrict__ Vth, const __nv_bfloat16* __restrict__ Vtl,
                  __nv_bfloat16* __restrict__ Oh, __nv_bfloat16* __restrict__ Ol)
{
    const int qt = blockIdx.x, bh = blockIdx.y;
    const int b = bh >> 3, h = bh & 7;
    const int tid = threadIdx.x;
    const size_t pbase = (size_t)bh * SEQ * SEQ;
    const int nch = (qt + 1) * 2;

    extern __shared__ char smem[];
    const int seg = tid & 7, r0 = tid >> 3;

    auto load_chunk = [&](int kc, int s) {
        char* base = smem + s * AO_STAGE;
        const size_t kk = (size_t)kc * 64 + seg * 8;
#pragma unroll
        for (int it = 0; it < 4; it++) {
            const int r = r0 + it * 32;
            const uint32_t dst = smem_u32(base + (r * LDP + seg * 8) * 2);
            cp16(dst,        Ph + pbase + (size_t)(qt * 128 + r) * SEQ + kk);
            cp16(dst + T128, Pl + pbase + (size_t)(qt * 128 + r) * SEQ + kk);
        }
#pragma unroll
        for (int it = 0; it < 2; it++) {
            const int r = r0 + it * 32;
            const uint32_t dst = smem_u32(base + 2 * T128 + (r * LDP + seg * 8) * 2);
            cp16(dst,       Vth + ((size_t)bh * HD + r) * SEQ + kk);
            cp16(dst + T64, Vtl + ((size_t)bh * HD + r) * SEQ + kk);
        }
        cp_commit();
    };

    load_chunk(0, 0);

    float acc[2][4][4];
#pragma unroll
    for (int i = 0; i < 2; i++)
#pragma unroll
        for (int j = 0; j < 4; j++)
#pragma unroll
            for (int c = 0; c < 4; c++) acc[i][j][c] = 0.f;

    const int lane = tid & 31, wid = tid >> 5;
    const int wm = wid >> 1, wn = wid & 1;
    const int lm_r = (lane & 7) + ((lane >> 3) & 1) * 8;
    const int lm_c = ((lane >> 4) & 1) * 8;
    const int lb_r = (lane & 7) + ((lane >> 4) & 1) * 8;
    const int lb_c = ((lane >> 3) & 1) * 8;

    for (int kc = 0; kc < nch; kc++) {
        const int s = kc & 1;
        cp_wait0();
        __syncthreads();
        if (kc + 1 < nch) load_chunk(kc + 1, s ^ 1);

        const __nv_bfloat16* sPh = (const __nv_bfloat16*)(smem + s * AO_STAGE);
        const __nv_bfloat16* sPl = (const __nv_bfloat16*)((char*)sPh + T128);
        const __nv_bfloat16* sVh = (const __nv_bfloat16*)((char*)sPh + 2 * T128);
        const __nv_bfloat16* sVl = (const __nv_bfloat16*)((char*)sPh + 2 * T128 + T64);

#pragma unroll
        for (int ks = 0; ks < 4; ks++) {
            const int k0 = ks * 16;
            uint32_t Ah[2][4], Al[2][4], Bh[4][2], Bl[4][2];
#pragma unroll
            for (int mi = 0; mi < 2; mi++) {
                const int r = wm * 32 + mi * 16 + lm_r;
                LDMX4(Ah[mi][0], Ah[mi][1], Ah[mi][2], Ah[mi][3], smem_u32(sPh + r * LDP + k0 + lm_c));
                LDMX4(Al[mi][0], Al[mi][1], Al[mi][2], Al[mi][3], smem_u32(sPl + r * LDP + k0 + lm_c));
            }
#pragma unroll
            for (int nio = 0; nio < 2; nio++) {
                const int r = wn * 32 + nio * 16 + lb_r;
                LDMX4(Bh[2*nio][0], Bh[2*nio][1], Bh[2*nio+1][0], Bh[2*nio+1][1],
                      smem_u32(sVh + r * LDP + k0 + lb_c));
                LDMX4(Bl[2*nio][0], Bl[2*nio][1], Bl[2*nio+1][0], Bl[2*nio+1][1],
                      smem_u32(sVl + r * LDP + k0 + lb_c));
            }
#pragma unroll
            for (int mi = 0; mi < 2; mi++)
#pragma unroll
                for (int ni = 0; ni < 4; ni++) MMA_BF16(acc[mi][ni], Ah[mi], Bh[ni]);
#pragma unroll
            for (int mi = 0; mi < 2; mi++)
#pragma unroll
                for (int ni = 0; ni < 4; ni++) MMA_BF16(acc[mi][ni], Ah[mi], Bl[ni]);
#pragma unroll
            for (int mi = 0; mi < 2; mi++)
#pragma unroll
                for (int ni = 0; ni < 4; ni++) MMA_BF16(acc[mi][ni], Al[mi], Bh[ni]);
        }
    }

    const int g = lane >> 2, t = lane & 3;
#pragma unroll
    for (int mi = 0; mi < 2; mi++) {
        const int q = qt * 128 + wm * 32 + mi * 16 + g;
#pragma unroll
        for (int ni = 0; ni < 4; ni++) {
            const int d = wn * 32 + ni * 8 + 2 * t;
            const size_t o0 = ((size_t)(b * SEQ + q) * DMODEL) + h * HD + d;
            const size_t o1 = ((size_t)(b * SEQ + q + 8) * DMODEL) + h * HD + d;
            float v00 = acc[mi][ni][0], v01 = acc[mi][ni][1];
            float v10 = acc[mi][ni][2], v11 = acc[mi][ni][3];
            __nv_bfloat16 h00 = __float2bfloat16(v00), h01 = __float2bfloat16(v01);
            __nv_bfloat16 h10 = __float2bfloat16(v10), h11 = __float2bfloat16(v11);
            *(uint32_t*)(Oh + o0) = pack2(h00, h01);
            *(uint32_t*)(Oh + o1) = pack2(h10, h11);
            *(uint32_t*)(Ol + o0) = pack2(__float2bfloat16(v00 - __bfloat162float(h00)),
                                          __float2bfloat16(v01 - __bfloat162float(h01)));
            *(uint32_t*)(Ol + o1) = pack2(__float2bfloat16(v10 - __bfloat162float(h10)),
                                          __float2bfloat16(v11 - __bfloat162float(h11)));
        }
    }
}

// ============ weight transpose + split ========================================
__global__ void transpose_convert_kernel(const float* __restrict__ W,
                                         __nv_bfloat16* __restrict__ Hi,
                                         __nv_bfloat16* __restrict__ Lo, int K, int N)
{
    __shared__ float t[32][33];
    const int k0 = blockIdx.y * 32, n0 = blockIdx.x * 32;
    const int tx = threadIdx.x & 31, ty = threadIdx.x >> 5;
#pragma unroll
    for (int j = 0; j < 32; j += 8)
        t[ty + j][tx] = W[(size_t)(k0 + ty + j) * N + n0 + tx];
    __syncthreads();
#pragma unroll
    for (int j = 0; j < 32; j += 8) {
        float v = t[tx][ty + j];
        __nv_bfloat16 h = __float2bfloat16(v);
        Hi[(size_t)(n0 + ty + j) * K + k0 + tx] = h;
        Lo[(size_t)(n0 + ty + j) * K + k0 + tx] = __float2bfloat16(v - __bfloat162float(h));
    }
}

// ============ elementwise split ===============================================
__global__ void split_kernel(const float* __restrict__ in,
                             __nv_bfloat16* __restrict__ hi, __nv_bfloat16* __restrict__ lo)
{
    const int i = blockIdx.x * 256 + threadIdx.x;
    float4 v = ((const float4*)in)[i];
    uint2 h, l;
    split4(v, h, l);
    ((uint2*)hi)[i] = h;
    ((uint2*)lo)[i] = l;
}

// ============ residual + LayerNorm ============================================
__global__ void ln_kernel(const float* __restrict__ xin, const float* __restrict__ res,
                          const float* __restrict__ scale, const float* __restrict__ bias,
                          float* __restrict__ outf,
                          __nv_bfloat16* __restrict__ outh, __nv_bfloat16* __restrict__ outl)
{
    const int row = blockIdx.x;
    const int tid = threadIdx.x;
    float4 v = ((const float4*)(xin + (size_t)row * DMODEL))[tid];
    if (res) {
        float4 r = ((const float4*)(res + (size_t)row * DMODEL))[tid];
        v.x += r.x; v.y += r.y; v.z += r.z; v.w += r.w;
    }
    float s  = v.x + v.y + v.z + v.w;
    float sq = v.x * v.x + v.y * v.y + v.z * v.z + v.w * v.w;
#pragma unroll
    for (int o = 16; o > 0; o >>= 1) {
        s  += __shfl_xor_sync(~0u, s,  o);
        sq += __shfl_xor_sync(~0u, sq, o);
    }
    __shared__ float ss[4], sqs[4];
    const int warp = tid >> 5, lane = tid & 31;
    if (lane == 0) { ss[warp] = s; sqs[warp] = sq; }
    __syncthreads();
    float S  = ss[0]  + ss[1]  + ss[2]  + ss[3];
    float SQ = sqs[0] + sqs[1] + sqs[2] + sqs[3];
    float mean = S * (1.f / DMODEL);
    float var  = SQ * (1.f / DMODEL) - mean * mean;
    float rs   = rsqrtf(var + 1e-6f);
    float4 sc4 = ((const float4*)scale)[tid];
    float4 bi4 = ((const float4*)bias)[tid];
    float4 o;
    o.x = (v.x - mean) * rs * sc4.x + bi4.x;
    o.y = (v.y - mean) * rs * sc4.y + bi4.y;
    o.z = (v.z - mean) * rs * sc4.z + bi4.z;
    o.w = (v.w - mean) * rs * sc4.w + bi4.w;
    if (outf) ((float4*)(outf + (size_t)row * DMODEL))[tid] = o;
    uint2 h, l;
    split4(o, h, l);
    ((uint2*)(outh + (size_t)row * DMODEL))[tid] = h;
    ((uint2*)(outl + (size_t)row * DMODEL))[tid] = l;
}

// ============ winner gather ===================================================
__global__ void gather_kernel(const unsigned long long* __restrict__ best,
                              const float* __restrict__ vs, const float* __restrict__ ss,
                              float* __restrict__ vout, float* __restrict__ sout)
{
    const int n = blockIdx.x;
    const int lane = threadIdx.x;
    const unsigned long long key = best[n];
    const int idx = (int)(~(unsigned int)(key & 0xFFFFFFFFull));
    vout[(size_t)n * OUTD + lane] = vs[(size_t)n * (NSLOTS * OUTD) + (size_t)idx * OUTD + lane];
    if (lane == 0) sout[n] = ss[(size_t)n * NSLOTS + idx];
}

// ---------------- host-side wrapper ----------------
struct Bufs {
    __nv_bfloat16 *bthi, *btlo;
};
static void tc_gemm(const __nv_bfloat16* Ah, const __nv_bfloat16* Al,
                    const float* W, const float* bias,
                    float* Cf, __nv_bfloat16* Chi, __nv_bfloat16* Clo,
                    int M, int N, int K, int relu, const Bufs& bf,
                    const float* xsc = nullptr, unsigned long long* best = nullptr)
{
    transpose_convert_kernel<<<dim3(N / 32, K / 32), 256>>>(W, bf.bthi, bf.btlo, K, N);
    gemm_bb_kernel<<<dim3(N / 128, M / 128), 512, GEMM_SMEM>>>(
        Ah, Al, bf.bthi, bf.btlo, bias, Cf, Chi, Clo, M, N, K, relu, xsc, best);
}

extern "C" void kernel_launch(void* const* d_in, const int* in_sizes, int n_in,
                              void* d_out, int out_size)
{
    const float* s_in  = (const float*)d_in[0];
    const float* x_in  = (const float*)d_in[1];
    const float* t_in  = (const float*)d_in[2];
    const float* Wq    = (const float*)d_in[3];
    const float* Wk    = (const float*)d_in[4];
    const float* Wv    = (const float*)d_in[5];
    const float* Wo    = (const float*)d_in[6];
    const float* cWv   = (const float*)d_in[9];
    const float* cWo   = (const float*)d_in[10];
    const float* ln1_s = (const float*)d_in[11];
    const float* ln1_b = (const float*)d_in[12];
    const float* ln2_s = (const float*)d_in[13];
    const float* ln2_b = (const float*)d_in[14];
    const float* ln3_s = (const float*)d_in[15];
    const float* ln3_b = (const float*)d_in[16];
    const float* W1    = (const float*)d_in[17];
    const float* b1    = (const float*)d_in[18];
    const float* W2    = (const float*)d_in[19];
    const float* b2    = (const float*)d_in[20];
    const float* lnf_s = (const float*)d_in[21];
    const float* lnf_b = (const float*)d_in[22];
    const float* Wout  = (const float*)d_in[23];
    const float* bout  = (const float*)d_in[24];
    const float* W_vs  = (const float*)d_in[25];
    const float* b_vs  = (const float*)d_in[26];
    const float* W_ss  = (const float*)d_in[27];
    const float* b_ss  = (const float*)d_in[28];
    float* out = (float*)d_out;

    float *dec, *vb, *tmp2, *sc, *vs;
    unsigned long long* best;
    __nv_bfloat16 *dech, *decl, *qbh, *qbl, *kbh, *kbl, *obh, *obl, *th, *tl;
    __nv_bfloat16 *ffh, *ffl, *keysh, *keysl, *ph, *pl, *vthi, *vtlo, *cvh, *cvl;
    Bufs bf;
    cudaGetSymbolAddress((void**)&dec,  g_dec);
    cudaGetSymbolAddress((void**)&vb,   g_vb);
    cudaGetSymbolAddress((void**)&tmp2, g_tmp2);
    cudaGetSymbolAddress((void**)&sc,   g_sc);
    cudaGetSymbolAddress((void**)&vs,   g_vs);
    cudaGetSymbolAddress((void**)&best, g_best);
    cudaGetSymbolAddress((void**)&dech, g_dech);
    cudaGetSymbolAddress((void**)&decl, g_decl);
    cudaGetSymbolAddress((void**)&qbh,  g_qbh);
    cudaGetSymbolAddress((void**)&qbl,  g_qbl);
    cudaGetSymbolAddress((void**)&kbh,  g_kbh);
    cudaGetSymbolAddress((void**)&kbl,  g_kbl);
    cudaGetSymbolAddress((void**)&obh,  g_obh);
    cudaGetSymbolAddress((void**)&obl,  g_obl);
    cudaGetSymbolAddress((void**)&th,   g_th);
    cudaGetSymbolAddress((void**)&tl,   g_tl);
    cudaGetSymbolAddress((void**)&ffh,  g_ffh);
    cudaGetSymbolAddress((void**)&ffl,  g_ffl);
    cudaGetSymbolAddress((void**)&keysh,g_keysh);
    cudaGetSymbolAddress((void**)&keysl,g_keysl);
    cudaGetSymbolAddress((void**)&ph,   g_ph);
    cudaGetSymbolAddress((void**)&pl,   g_pl);
    cudaGetSymbolAddress((void**)&vthi, g_vthi);
    cudaGetSymbolAddress((void**)&vtlo, g_vtlo);
    cudaGetSymbolAddress((void**)&cvh,  g_cvh);
    cudaGetSymbolAddress((void**)&cvl,  g_cvl);
    cudaGetSymbolAddress((void**)&bf.bthi, g_bthi);
    cudaGetSymbolAddress((void**)&bf.btlo, g_btlo);

    cudaFuncSetAttribute(gemm_bb_kernel,  cudaFuncAttributeMaxDynamicSharedMemorySize, GEMM_SMEM);
    cudaFuncSetAttribute(attn_scores_mma, cudaFuncAttributeMaxDynamicSharedMemorySize, ASC_SMEM);
    cudaFuncSetAttribute(attn_out_mma,    cudaFuncAttributeMaxDynamicSharedMemorySize, AO_SMEM);

    cudaMemcpyAsync(dec, s_in, sizeof(float) * NTOK * DMODEL, cudaMemcpyDeviceToDevice);
    cudaMemsetAsync(best, 0, NTOK * sizeof(unsigned long long));
    split_kernel<<<NTOK * DMODEL / 1024, 256>>>(s_in, dech, decl);
    split_kernel<<<NTOK * DMODEL / 1024, 256>>>(t_in, th, tl);
    split_kernel<<<2 * DMODEL * DMODEL / 1024, 256>>>(cWv, cvh, cvl);   // both layers

    for (int l = 0; l < 2; l++) {
        const size_t wo = (size_t)l * DMODEL * DMODEL;
        // causal self-attention
        tc_gemm(dech, decl, Wq + wo, nullptr, nullptr, qbh, qbl, NTOK, DMODEL, DMODEL, 0, bf);
        tc_gemm(dech, decl, Wk + wo, nullptr, nullptr, kbh, kbl, NTOK, DMODEL, DMODEL, 0, bf);
        tc_gemm(dech, decl, Wv + wo, nullptr, vb, nullptr, nullptr, NTOK, DMODEL, DMODEL, 0, bf);
        attn_scores_mma<<<dim3(8, 8, 64), 256, ASC_SMEM>>>(qbh, qbl, kbh, kbl, sc);
        softmax_causal_kernel<<<dim3(SEQ, 64), 256>>>(sc, ph, pl);
        vt_convert_kernel<<<dim3(32, 2, 64), 256>>>(vb, vthi, vtlo);
        attn_out_mma<<<dim3(8, 64), 256, AO_SMEM>>>(ph, pl, vthi, vtlo, obh, obl);
        tc_gemm(obh, obl, Wo + wo, nullptr, tmp2, nullptr, nullptr, NTOK, DMODEL, DMODEL, 0, bf);
        ln_kernel<<<NTOK, 128>>>(dec, tmp2, ln1_s + l * DMODEL, ln1_b + l * DMODEL, dec, dech, decl);
        // cross-attention: Mx = cWv @ cWo (tiny), then tmp2 = t @ Mx (one unit GEMM)
        tc_gemm(cvh + wo, cvl + wo, cWo + wo, nullptr, vb, nullptr, nullptr,
                DMODEL, DMODEL, DMODEL, 0, bf);                         // vb = Mx
        tc_gemm(th, tl, vb, nullptr, tmp2, nullptr, nullptr, NTOK, DMODEL, DMODEL, 0, bf);
        ln_kernel<<<NTOK, 128>>>(dec, tmp2, ln2_s + l * DMODEL, ln2_b + l * DMODEL, dec, dech, decl);
        // FFN
        tc_gemm(dech, decl, W1 + (size_t)l * DMODEL * FFDIM, b1 + (size_t)l * FFDIM,
                nullptr, ffh, ffl, NTOK, FFDIM, DMODEL, 1, bf);
        tc_gemm(ffh, ffl, W2 + (size_t)l * FFDIM * DMODEL, b2 + (size_t)l * DMODEL,
                tmp2, nullptr, nullptr, NTOK, DMODEL, FFDIM, 0, bf);
        ln_kernel<<<NTOK, 128>>>(dec, tmp2, ln3_s + l * DMODEL, ln3_b + l * DMODEL, dec, dech, decl);
    }

    // final head
    ln_kernel<<<NTOK, 128>>>(dec, nullptr, lnf_s, lnf_b, nullptr, qbh, qbl);
    tc_gemm(qbh, qbl, Wout, bout, tmp2, nullptr, nullptr, NTOK, DMODEL, DMODEL, 0, bf);
    softmax_keys_kernel<<<NTOK, 256>>>(tmp2, keysh, keysl);

    float* out_v  = out;
    float* out_s  = out + 262144;
    float* out_ss = out + 262144 + 8192;

    tc_gemm(keysh, keysl, W_ss, b_ss, out_ss, nullptr, nullptr, NTOK, NSLOTS, DMODEL, 0, bf);
    tc_gemm(keysh, keysl, W_vs, b_vs, vs, nullptr, nullptr, NTOK, NSLOTS * OUTD, DMODEL, 0, bf,
            x_in, best);
    gather_kernel<<<NTOK, 32>>>(best, vs, out_ss, out_v, out_s);
}